// round 1
// baseline (speedup 1.0000x reference)
#include <cuda_runtime.h>
#include <cstdint>
#include <math.h>

// Problem dims (fixed by the dataset)
#define BB 16
#define CC 64
#define HH 32
#define WW 32
#define TT 30
#define NF (TT*BB)          // 480 frames
#define FR1 (CC*HH*WW)      // 65536 elements per 32x32 frame
#define FR2 (CC*16*16)      // 16384 elements per 16x16 frame
#define FS  (BB*FR1)        // 1048576  (one [B,C,H,W] tensor)
#define FS2 (BB*FR2)        // 262144   (one [B,C,H/2,W/2] tensor)

// -------- scratch (device globals: the sanctioned no-alloc workaround) ------
__device__ float         g_utr[NF*FR1];   // u transposed to [t*B+b, C, H, W]
__device__ float         g_ca [NF*FR1];   // conv(u_t, W_in) for all t
__device__ unsigned char g_sa [NF*FR1];   // spikes s_a[t] (0/1)
__device__ float         g_cb [NF*FR2];   // conv(s_a[t], W_down, s2)
__device__ float         g_za [FS];       // firing rate a-scale
__device__ float         g_acc[FS];       // sum coef[t]*c_a[t] / norm
__device__ float         g_zb [FS2];      // firing rate b-scale
__device__ float         g_tmp[FS2];      // conv(z_b, W_bb)

// -------- packed f32x2 helpers ---------------------------------------------
__device__ __forceinline__ unsigned long long pack2(float lo, float hi) {
    unsigned long long r;
    asm("mov.b64 %0, {%1, %2};" : "=l"(r) : "f"(lo), "f"(hi));
    return r;
}
__device__ __forceinline__ void unpack2(unsigned long long v, float& lo, float& hi) {
    asm("mov.b64 {%0, %1}, %2;" : "=f"(lo), "=f"(hi) : "l"(v));
}
__device__ __forceinline__ unsigned long long fma2(unsigned long long a,
                                                   unsigned long long b,
                                                   unsigned long long c) {
    unsigned long long d;
    asm("fma.rn.f32x2 %0, %1, %2, %3;" : "=l"(d) : "l"(a), "l"(b), "l"(c));
    return d;
}

// -------- transpose u[B,C,H,W,T] -> g_utr[(t*B+b),C,H,W] --------------------
// block handles (b, c, h-group of 8): reads 7680 contiguous floats, writes
// 30 coalesced 256-float segments.
__global__ void __launch_bounds__(256) transpose_u(const float* __restrict__ u) {
    __shared__ float sm[8*32*TT];  // 7680 floats
    const int bid = blockIdx.x;
    const int b  = bid >> 8;
    const int c  = (bid >> 2) & 63;
    const int hg = bid & 3;
    const long long base = ((long long)(b*CC + c)*32 + hg*8) * (32*TT);
    for (int i = threadIdx.x; i < 8*32*TT; i += 256) sm[i] = u[base + i];
    __syncthreads();
    for (int i = threadIdx.x; i < 8*32*TT; i += 256) {
        int t  = i >> 8;      // 0..29
        int hw = i & 255;     // 0..255
        g_utr[((long long)(t*BB + b)*CC + c)*(HH*WW) + hg*256 + hw] = sm[hw*TT + t];
    }
}

// -------- generic 3x3 conv, SAME padding (JAX semantics), OIHW weights ------
// STRIDE==1: pad_lo=1 (symmetric). STRIDE==2: pad_lo=0, pad_hi=1 (asymmetric!)
// Block: 256 threads; 8 warps = 8 groups of 8 c_out (as 4 f32x2 pairs).
// Each thread: x column (or half-warp split for WO=16), RB output rows.
template<int HI, int WI, int STRIDE, typename Tin, bool FUSE>
__global__ void __launch_bounds__(256) conv3x3(const Tin* __restrict__ in,
                                               const float* __restrict__ wts,
                                               float* __restrict__ out,
                                               const float* __restrict__ addend) {
    constexpr int HO   = HI / STRIDE, WO = WI / STRIDE;
    constexpr int XPT  = (WO >= 32) ? 32 : WO;     // x lanes per warp
    constexpr int LSPL = 32 / XPT;                 // 1 or 2 row-splits
    constexpr int RB   = (STRIDE == 1) ? 4 : 2;    // output rows per thread
    constexpr int RBL  = RB * LSPL;                // output rows per block
    constexpr int IN_ROWS = (STRIDE == 1) ? (RBL + 2) : (2*RBL + 1);
    constexpr int IN_COLS = (STRIDE == 1) ? (WI + 2) : (WI + 1);
    constexpr int CKN = 8;                         // c_in chunk
    constexpr int NR  = (STRIDE == 1) ? (RB + 2) : (2*RB + 1);

    // input values stored duplicated {v,v} so FFMA2 broadcast comes from LDS.64
    __shared__ unsigned long long ism[CKN][IN_ROWS][IN_COLS];
    __shared__ float wsm[CKN][9][64];              // [ci][tap][c_out]

    const int f     = blockIdx.x;
    const int r0blk = blockIdx.y * RBL;
    const int lane  = threadIdx.x & 31;
    const int warp  = threadIdx.x >> 5;
    const int x     = lane % XPT;
    const int ysub  = lane / XPT;
    const int co0   = warp * 8;
    const int rbase = r0blk + ysub * RB;
    const int row0_in = (STRIDE == 1) ? (r0blk - 1) : (2*r0blk);
    const int col0_in = (STRIDE == 1) ? -1 : 0;

    unsigned long long acc[4][RB];
#pragma unroll
    for (int p = 0; p < 4; ++p)
#pragma unroll
        for (int r = 0; r < RB; ++r) acc[p][r] = 0ULL;

    const long long inbase = (long long)f * CC * HI * WI;

    for (int cc = 0; cc < CC; cc += CKN) {
        // weights chunk -> smem (co contiguous; coalesced smem writes)
        for (int i = threadIdx.x; i < CKN*9*64; i += 256) {
            int ci  = i / 576;
            int rem = i - ci*576;
            int tap = rem >> 6;
            int co  = rem & 63;
            wsm[ci][tap][co] = wts[(co*CC + cc + ci)*9 + tap];
        }
        // input tile chunk -> smem (zero-padded, duplicated)
        for (int i = threadIdx.x; i < CKN*IN_ROWS*IN_COLS; i += 256) {
            int ci  = i / (IN_ROWS*IN_COLS);
            int rem = i - ci*(IN_ROWS*IN_COLS);
            int r   = rem / IN_COLS;
            int c2  = rem - r*IN_COLS;
            int gy = row0_in + r, gx = col0_in + c2;
            float v = 0.f;
            if ((unsigned)gy < (unsigned)HI && (unsigned)gx < (unsigned)WI)
                v = (float)in[inbase + (long long)(cc+ci)*(HI*WI) + gy*WI + gx];
            ism[ci][r][c2] = pack2(v, v);
        }
        __syncthreads();

        for (int ci = 0; ci < CKN; ++ci) {
            unsigned long long bv[NR][3];
#pragma unroll
            for (int j = 0; j < NR; ++j) {
                const int srow = ((STRIDE == 1) ? (ysub*RB) : (2*ysub*RB)) + j;
#pragma unroll
                for (int kx = 0; kx < 3; ++kx) {
                    const int scol = ((STRIDE == 1) ? x : 2*x) + kx;
                    bv[j][kx] = ism[ci][srow][scol];
                }
            }
#pragma unroll
            for (int p = 0; p < 4; ++p) {
                unsigned long long w2[9];
#pragma unroll
                for (int tap = 0; tap < 9; ++tap)
                    w2[tap] = *reinterpret_cast<const unsigned long long*>(
                        &wsm[ci][tap][co0 + 2*p]);
#pragma unroll
                for (int r = 0; r < RB; ++r) {
#pragma unroll
                    for (int ky = 0; ky < 3; ++ky) {
                        const int j = (STRIDE == 1) ? (r + ky) : (2*r + ky);
#pragma unroll
                        for (int kx = 0; kx < 3; ++kx)
                            acc[p][r] = fma2(bv[j][kx], w2[3*ky + kx], acc[p][r]);
                    }
                }
            }
        }
        __syncthreads();
    }

#pragma unroll
    for (int p = 0; p < 4; ++p) {
#pragma unroll
        for (int r = 0; r < RB; ++r) {
            float lo, hi;
            unpack2(acc[p][r], lo, hi);
            const int oy = rbase + r;
            const long long o0 = (long long)f*CC*HO*WO
                               + (long long)(co0 + 2*p)*HO*WO + oy*WO + x;
            if (FUSE) {
                lo += addend[o0];
                hi += addend[o0 + HO*WO];
                lo = fminf(fmaxf(lo, 0.f), 1.f);
                hi = fminf(fmaxf(hi, 0.f), 1.f);
            }
            out[o0]          = lo;
            out[o0 + HO*WO]  = hi;
        }
    }
}

// -------- scan A: LIF over t (elementwise) + fused u_bar weighted conv sum --
__global__ void __launch_bounds__(256) scanA_kernel() {
    const int p = blockIdx.x * blockDim.x + threadIdx.x;
    // coef[t] = 0.9^(29-t) for t<29 ; coef[29] = 1 + 0.9^30 (wraparound term)
    float coef[TT];
    float pw = 1.f;
#pragma unroll
    for (int k = 1; k <= TT-1; ++k) { pw *= 0.9f; coef[TT-1-k] = pw; }
    coef[TT-1] = 1.0f + pw * 0.9f;
    const float norm = (float)((1.0 - pow(0.9, (double)(TT+1))) / (1.0 - 0.9));

    float v = 0.f, ssum = 0.f, ac = 0.f;
#pragma unroll
    for (int t = 0; t < TT; ++t) {
        const float cv = g_ca[(long long)t*FS + p];
        ac = fmaf(coef[t], cv, ac);
        v = 0.5f*v + cv;
        const float s = (v >= 1.0f) ? 1.0f : 0.0f;
        v -= s;
        ssum += s;
        g_sa[(long long)t*FS + p] = (unsigned char)s;
    }
    g_za[p]  = ssum / 30.0f;
    g_acc[p] = ac / norm;
}

// -------- scan B: LIF over t at half resolution ----------------------------
__global__ void __launch_bounds__(256) scanB_kernel() {
    const int p = blockIdx.x * blockDim.x + threadIdx.x;
    float v = 0.f, ssum = 0.f;
#pragma unroll
    for (int t = 0; t < TT; ++t) {
        const float cv = g_cb[(long long)t*FS2 + p];
        v = 0.5f*v + cv;
        const float s = (v >= 1.0f) ? 1.0f : 0.0f;
        v -= s;
        ssum += s;
    }
    g_zb[p] = ssum / 30.0f;
}

// ---------------------------------------------------------------------------
extern "C" void kernel_launch(void* const* d_in, const int* in_sizes, int n_in,
                              void* d_out, int out_size) {
    const float* u      = (const float*)d_in[0];
    const float* W_in   = (const float*)d_in[1];
    const float* W_aa   = (const float*)d_in[2];
    const float* W_down = (const float*)d_in[3];
    const float* W_bb   = (const float*)d_in[4];
    float* out = (float*)d_out;

    float *p_utr, *p_ca, *p_cb, *p_za, *p_acc, *p_zb, *p_tmp;
    unsigned char *p_sa;
    cudaGetSymbolAddress((void**)&p_utr, g_utr);
    cudaGetSymbolAddress((void**)&p_ca,  g_ca);
    cudaGetSymbolAddress((void**)&p_sa,  g_sa);
    cudaGetSymbolAddress((void**)&p_cb,  g_cb);
    cudaGetSymbolAddress((void**)&p_za,  g_za);
    cudaGetSymbolAddress((void**)&p_acc, g_acc);
    cudaGetSymbolAddress((void**)&p_zb,  g_zb);
    cudaGetSymbolAddress((void**)&p_tmp, g_tmp);

    // 1. transpose u -> frame-major
    transpose_u<<<BB*CC*4, 256>>>(u);
    // 2. c_a[t] = conv(u_t, W_in) for all 480 frames
    conv3x3<32,32,1,float,false><<<dim3(NF,8), 256>>>(p_utr, W_in, p_ca, nullptr);
    // 3. LIF scan A (spikes + rates + fused u_bar-conv sum)
    scanA_kernel<<<FS/256, 256>>>();
    // 4. c_b[t] = conv(s_a[t], W_down, stride2) for all 480 frames
    conv3x3<32,32,2,unsigned char,false><<<dim3(NF,4), 256>>>(p_sa, W_down, p_cb, nullptr);
    // 5. LIF scan B
    scanB_kernel<<<FS2/256, 256>>>();
    // 6. a = clip(acc + conv(z_a, W_aa))            -> d_out[0 : FS)
    conv3x3<32,32,1,float,true><<<dim3(BB,8), 256>>>(p_za, W_aa, out, p_acc);
    // 7a. tmp = conv(z_b, W_bb)  (stride-1 on 16x16)
    conv3x3<16,16,1,float,false><<<dim3(BB,2), 256>>>(p_zb, W_bb, p_tmp, nullptr);
    // 7b. b = clip(conv(a, W_down, stride2) + tmp)  -> d_out[FS : FS+FS2)
    conv3x3<32,32,2,float,true><<<dim3(BB,4), 256>>>(out, W_down, out + FS, p_tmp);
}

// round 4
// speedup vs baseline: 1.1248x; 1.1248x over previous
#include <cuda_runtime.h>
#include <cstdint>
#include <math.h>

// Problem dims (fixed by the dataset)
#define BB 16
#define CC 64
#define HH 32
#define WW 32
#define TT 30
#define NF (TT*BB)          // 480 frames
#define FR1 (CC*HH*WW)      // 65536 elements per 32x32 frame
#define FR2 (CC*16*16)      // 16384 elements per 16x16 frame
#define FS  (BB*FR1)        // 1048576  (one [B,C,H,W] tensor)
#define FS2 (BB*FR2)        // 262144   (one [B,C,H/2,W/2] tensor)

typedef unsigned long long u64;

// -------- scratch (device globals: the sanctioned no-alloc workaround) ------
__device__ float         g_utr[NF*FR1];   // u transposed to [t*B+b, C, H, W]
__device__ float         g_ca [NF*FR1];   // conv(u_t, W_in) for all t
__device__ unsigned char g_sa [NF*FR1];   // spikes s_a[t] (0/1)
__device__ float         g_cb [NF*FR2];   // conv(s_a[t], W_down, s2)
__device__ float         g_za [FS];       // firing rate a-scale
__device__ float         g_acc[FS];       // sum coef[t]*c_a[t] / norm
__device__ float         g_zb [FS2];      // firing rate b-scale
__device__ float         g_tmp[FS2];      // conv(z_b, W_bb)

// -------- packed f32x2 helpers ---------------------------------------------
__device__ __forceinline__ u64 dup2(float v) {          // {v, v}
    u64 r;
    asm("mov.b64 %0, {%1, %1};" : "=l"(r) : "f"(v));
    return r;
}
__device__ __forceinline__ void unpack2(u64 v, float& lo, float& hi) {
    asm("mov.b64 {%0, %1}, %2;" : "=f"(lo), "=f"(hi) : "l"(v));
}
__device__ __forceinline__ u64 fma2(u64 a, u64 b, u64 c) {
    u64 d;
    asm("fma.rn.f32x2 %0, %1, %2, %3;" : "=l"(d) : "l"(a), "l"(b), "l"(c));
    return d;
}

// -------- transpose u[B,C,H,W,T] -> g_utr[(t*B+b),C,H,W] --------------------
__global__ void __launch_bounds__(256) transpose_u(const float* __restrict__ u) {
    __shared__ float sm[8*32*TT];  // 7680 floats
    const int bid = blockIdx.x;
    const int b  = bid >> 8;
    const int c  = (bid >> 2) & 63;
    const int hg = bid & 3;
    const long long base = ((long long)(b*CC + c)*32 + hg*8) * (32*TT);
    for (int i = threadIdx.x; i < 8*32*TT; i += 256) sm[i] = u[base + i];
    __syncthreads();
    for (int i = threadIdx.x; i < 8*32*TT; i += 256) {
        int t  = i >> 8;
        int hw = i & 255;
        g_utr[((long long)(t*BB + b)*CC + c)*(HH*WW) + hg*256 + hw] = sm[hw*TT + t];
    }
}

// ============================================================================
// stride-1 3x3 conv, SAME padding (pad_lo=1), OIHW weights.
// smem inputs stored as plain f32 (LDS.32 + register dup for FFMA2 broadcast).
// 8 warps x 8 c_out each (4 f32x2 pairs). RB=4 output rows per thread.
// ============================================================================
template<int HI, int WI, typename Tin, bool FUSE>
__global__ void __launch_bounds__(256, 2) conv_s1(const Tin* __restrict__ in,
                                                  const float* __restrict__ wts,
                                                  float* __restrict__ out,
                                                  const float* __restrict__ addend) {
    constexpr int HO = HI, WO = WI;
    constexpr int XPT  = (WO >= 32) ? 32 : WO;
    constexpr int LSPL = 32 / XPT;
    constexpr int RB   = 4;
    constexpr int RBL  = RB * LSPL;
    constexpr int IN_ROWS = RBL + 2;
    constexpr int IN_COLS = WI + 2;
    constexpr int CKN = 8;
    constexpr int NR  = RB + 2;

    __shared__ float ism[CKN][IN_ROWS][IN_COLS];
    __shared__ alignas(16) float wsm[CKN][9][64];

    const int f     = blockIdx.x;
    const int r0blk = blockIdx.y * RBL;
    const int lane  = threadIdx.x & 31;
    const int warp  = threadIdx.x >> 5;
    const int x     = lane % XPT;
    const int ysub  = lane / XPT;
    const int co0   = warp * 8;
    const int rbase = r0blk + ysub * RB;

    u64 acc[4][RB];
#pragma unroll
    for (int p = 0; p < 4; ++p)
#pragma unroll
        for (int r = 0; r < RB; ++r) acc[p][r] = 0ULL;

    const long long inbase = (long long)f * CC * HI * WI;

    for (int cc = 0; cc < CC; cc += CKN) {
        for (int i = threadIdx.x; i < CKN*9*64; i += 256) {
            int ci  = i / 576;
            int rem = i - ci*576;
            int tap = rem >> 6;
            int co  = rem & 63;
            wsm[ci][tap][co] = wts[(co*CC + cc + ci)*9 + tap];
        }
        for (int i = threadIdx.x; i < CKN*IN_ROWS*IN_COLS; i += 256) {
            int ci  = i / (IN_ROWS*IN_COLS);
            int rem = i - ci*(IN_ROWS*IN_COLS);
            int r   = rem / IN_COLS;
            int c2  = rem - r*IN_COLS;
            int gy = r0blk - 1 + r, gx = c2 - 1;
            float v = 0.f;
            if ((unsigned)gy < (unsigned)HI && (unsigned)gx < (unsigned)WI)
                v = (float)in[inbase + (long long)(cc+ci)*(HI*WI) + gy*WI + gx];
            ism[ci][r][c2] = v;
        }
        __syncthreads();

        for (int ci = 0; ci < CKN; ++ci) {
            float bvf[NR][3];
#pragma unroll
            for (int j = 0; j < NR; ++j) {
                const int srow = ysub*RB + j;
#pragma unroll
                for (int kx = 0; kx < 3; ++kx)
                    bvf[j][kx] = ism[ci][srow][x + kx];
            }
            u64 bv[NR][3];
#pragma unroll
            for (int j = 0; j < NR; ++j)
#pragma unroll
                for (int kx = 0; kx < 3; ++kx)
                    bv[j][kx] = dup2(bvf[j][kx]);
#pragma unroll
            for (int p = 0; p < 4; ++p) {
                u64 w2[9];
#pragma unroll
                for (int tap = 0; tap < 9; ++tap)
                    w2[tap] = *reinterpret_cast<const u64*>(&wsm[ci][tap][co0 + 2*p]);
#pragma unroll
                for (int r = 0; r < RB; ++r)
#pragma unroll
                    for (int ky = 0; ky < 3; ++ky)
#pragma unroll
                        for (int kx = 0; kx < 3; ++kx)
                            acc[p][r] = fma2(bv[r+ky][kx], w2[3*ky + kx], acc[p][r]);
            }
        }
        __syncthreads();
    }

#pragma unroll
    for (int p = 0; p < 4; ++p) {
#pragma unroll
        for (int r = 0; r < RB; ++r) {
            float lo, hi;
            unpack2(acc[p][r], lo, hi);
            const int oy = rbase + r;
            const long long o0 = (long long)f*CC*HO*WO
                               + (long long)(co0 + 2*p)*HO*WO + oy*WO + x;
            if (FUSE) {
                lo += addend[o0];
                hi += addend[o0 + HO*WO];
                lo = fminf(fmaxf(lo, 0.f), 1.f);
                hi = fminf(fmaxf(hi, 0.f), 1.f);
            }
            out[o0]         = lo;
            out[o0 + HO*WO] = hi;
        }
    }
}

// ============================================================================
// stride-2 3x3 conv 32x32 -> 16x16, SAME (pad_lo=0, pad_hi=1 — JAX asymmetric).
// Deinterleaved even/odd column planes: conflict-free lane reads.
//   out col x taps: in[2x]=evn[x], in[2x+1]=odd[x], in[2x+2]=evn[x+1]
// 8 warps x 8 c_out; warp = 16 x-lanes x 2 ysub; RB=4 rows/thread; grid.y=2.
// ============================================================================
template<typename Tin, bool FUSE>
__global__ void __launch_bounds__(256, 2) conv_s2(const Tin* __restrict__ in,
                                                  const float* __restrict__ wts,
                                                  float* __restrict__ out,
                                                  const float* __restrict__ addend) {
    constexpr int HI = 32, WI = 32, HO = 16, WO = 16;
    constexpr int RB = 4;
    constexpr int IN_ROWS = 17;           // 2*8+1 input rows per block
    constexpr int CKN = 8;
    constexpr int NR = 2*RB + 1;          // 9 input rows per thread

    __shared__ float evn[CKN][IN_ROWS][17];   // row stride 17 floats
    __shared__ float odd[CKN][IN_ROWS][16];   // row stride 16: disjoint half-warp banks
    __shared__ alignas(16) float wsm[CKN][9][64];

    const int f    = blockIdx.x;
    const int yb   = blockIdx.y;          // 0/1
    const int lane = threadIdx.x & 31;
    const int warp = threadIdx.x >> 5;
    const int x    = lane & 15;
    const int ysub = lane >> 4;
    const int co0  = warp * 8;
    const int rbase = yb*8 + ysub*RB;
    const int r0in  = 16*yb;

    u64 acc[4][RB];
#pragma unroll
    for (int p = 0; p < 4; ++p)
#pragma unroll
        for (int r = 0; r < RB; ++r) acc[p][r] = 0ULL;

    const long long inbase = (long long)f * CC * HI * WI;

    for (int cc = 0; cc < CC; cc += CKN) {
        for (int i = threadIdx.x; i < CKN*9*64; i += 256) {
            int ci  = i / 576;
            int rem = i - ci*576;
            int tap = rem >> 6;
            int co  = rem & 63;
            wsm[ci][tap][co] = wts[(co*CC + cc + ci)*9 + tap];
        }
        // input rows r0in..r0in+16, cols 0..32 (col 32 & row 32 are zero pad)
        for (int i = threadIdx.x; i < CKN*IN_ROWS*33; i += 256) {
            int ci  = i / (IN_ROWS*33);
            int rem = i - ci*(IN_ROWS*33);
            int r   = rem / 33;
            int c2  = rem - r*33;
            int gy = r0in + r;
            float v = 0.f;
            if (gy < HI && c2 < WI)
                v = (float)in[inbase + (long long)(cc+ci)*(HI*WI) + gy*WI + c2];
            if (c2 & 1) odd[ci][r][c2 >> 1] = v;
            else        evn[ci][r][c2 >> 1] = v;
        }
        __syncthreads();

        for (int ci = 0; ci < CKN; ++ci) {
            float bvf[NR][3];
#pragma unroll
            for (int j = 0; j < NR; ++j) {
                const int srow = 8*ysub + j;
                bvf[j][0] = evn[ci][srow][x];
                bvf[j][1] = odd[ci][srow][x];
                bvf[j][2] = evn[ci][srow][x + 1];
            }
            u64 bv[NR][3];
#pragma unroll
            for (int j = 0; j < NR; ++j)
#pragma unroll
                for (int kx = 0; kx < 3; ++kx)
                    bv[j][kx] = dup2(bvf[j][kx]);
#pragma unroll
            for (int p = 0; p < 4; ++p) {
                u64 w2[9];
#pragma unroll
                for (int tap = 0; tap < 9; ++tap)
                    w2[tap] = *reinterpret_cast<const u64*>(&wsm[ci][tap][co0 + 2*p]);
#pragma unroll
                for (int r = 0; r < RB; ++r)
#pragma unroll
                    for (int ky = 0; ky < 3; ++ky)
#pragma unroll
                        for (int kx = 0; kx < 3; ++kx)
                            acc[p][r] = fma2(bv[2*r+ky][kx], w2[3*ky + kx], acc[p][r]);
            }
        }
        __syncthreads();
    }

#pragma unroll
    for (int p = 0; p < 4; ++p) {
#pragma unroll
        for (int r = 0; r < RB; ++r) {
            float lo, hi;
            unpack2(acc[p][r], lo, hi);
            const int oy = rbase + r;
            const long long o0 = (long long)f*CC*HO*WO
                               + (long long)(co0 + 2*p)*HO*WO + oy*WO + x;
            if (FUSE) {
                lo += addend[o0];
                hi += addend[o0 + HO*WO];
                lo = fminf(fmaxf(lo, 0.f), 1.f);
                hi = fminf(fmaxf(hi, 0.f), 1.f);
            }
            out[o0]         = lo;
            out[o0 + HO*WO] = hi;
        }
    }
}

// -------- scan A: LIF over t (elementwise) + fused u_bar weighted conv sum --
__global__ void __launch_bounds__(256) scanA_kernel() {
    const int p = blockIdx.x * blockDim.x + threadIdx.x;
    float coef[TT];
    float pw = 1.f;
#pragma unroll
    for (int k = 1; k <= TT-1; ++k) { pw *= 0.9f; coef[TT-1-k] = pw; }
    coef[TT-1] = 1.0f + pw * 0.9f;
    const float norm = (float)((1.0 - pow(0.9, (double)(TT+1))) / (1.0 - 0.9));

    float v = 0.f, ssum = 0.f, ac = 0.f;
#pragma unroll
    for (int t = 0; t < TT; ++t) {
        const float cv = g_ca[(long long)t*FS + p];
        ac = fmaf(coef[t], cv, ac);
        v = 0.5f*v + cv;
        const float s = (v >= 1.0f) ? 1.0f : 0.0f;
        v -= s;
        ssum += s;
        g_sa[(long long)t*FS + p] = (unsigned char)s;
    }
    g_za[p]  = ssum / 30.0f;
    g_acc[p] = ac / norm;
}

// -------- scan B: LIF over t at half resolution ----------------------------
__global__ void __launch_bounds__(256) scanB_kernel() {
    const int p = blockIdx.x * blockDim.x + threadIdx.x;
    float v = 0.f, ssum = 0.f;
#pragma unroll
    for (int t = 0; t < TT; ++t) {
        const float cv = g_cb[(long long)t*FS2 + p];
        v = 0.5f*v + cv;
        const float s = (v >= 1.0f) ? 1.0f : 0.0f;
        v -= s;
        ssum += s;
    }
    g_zb[p] = ssum / 30.0f;
}

// ---------------------------------------------------------------------------
extern "C" void kernel_launch(void* const* d_in, const int* in_sizes, int n_in,
                              void* d_out, int out_size) {
    const float* u      = (const float*)d_in[0];
    const float* W_in   = (const float*)d_in[1];
    const float* W_aa   = (const float*)d_in[2];
    const float* W_down = (const float*)d_in[3];
    const float* W_bb   = (const float*)d_in[4];
    float* out = (float*)d_out;

    float *p_utr, *p_ca, *p_cb, *p_za, *p_acc, *p_zb, *p_tmp;
    unsigned char *p_sa;
    cudaGetSymbolAddress((void**)&p_utr, g_utr);
    cudaGetSymbolAddress((void**)&p_ca,  g_ca);
    cudaGetSymbolAddress((void**)&p_sa,  g_sa);
    cudaGetSymbolAddress((void**)&p_cb,  g_cb);
    cudaGetSymbolAddress((void**)&p_za,  g_za);
    cudaGetSymbolAddress((void**)&p_acc, g_acc);
    cudaGetSymbolAddress((void**)&p_zb,  g_zb);
    cudaGetSymbolAddress((void**)&p_tmp, g_tmp);

    // 1. transpose u -> frame-major
    transpose_u<<<BB*CC*4, 256>>>(u);
    // 2. c_a[t] = conv(u_t, W_in) for all 480 frames
    conv_s1<32,32,float,false><<<dim3(NF,8), 256>>>(p_utr, W_in, p_ca, nullptr);
    // 3. LIF scan A (spikes + rates + fused u_bar-conv sum)
    scanA_kernel<<<FS/256, 256>>>();
    // 4. c_b[t] = conv(s_a[t], W_down, stride2) for all 480 frames
    conv_s2<unsigned char,false><<<dim3(NF,2), 256>>>(p_sa, W_down, p_cb, nullptr);
    // 5. LIF scan B
    scanB_kernel<<<FS2/256, 256>>>();
    // 6. a = clip(acc + conv(z_a, W_aa))            -> d_out[0 : FS)
    conv_s1<32,32,float,true><<<dim3(BB,8), 256>>>(p_za, W_aa, out, p_acc);
    // 7a. tmp = conv(z_b, W_bb)  (stride-1 on 16x16)
    conv_s1<16,16,float,false><<<dim3(BB,2), 256>>>(p_zb, W_bb, p_tmp, nullptr);
    // 7b. b = clip(conv(a, W_down, stride2) + tmp)  -> d_out[FS : FS+FS2)
    conv_s2<float,true><<<dim3(BB,2), 256>>>(out, W_down, out + FS, p_tmp);
}

// round 5
// speedup vs baseline: 1.1435x; 1.0166x over previous
#include <cuda_runtime.h>
#include <cstdint>
#include <math.h>

// Problem dims (fixed by the dataset)
#define BB 16
#define CC 64
#define HH 32
#define WW 32
#define TT 30
#define NF (TT*BB)          // 480 frames
#define FR1 (CC*HH*WW)      // 65536 elements per 32x32 frame
#define FR2 (CC*16*16)      // 16384 elements per 16x16 frame
#define FS  (BB*FR1)        // 1048576  (one [B,C,H,W] tensor)
#define FS2 (BB*FR2)        // 262144   (one [B,C,H/2,W/2] tensor)

typedef unsigned long long u64;

// -------- scratch (device globals: the sanctioned no-alloc workaround) ------
__device__ float         g_utr[NF*FR1];   // u transposed to [t*B+b, C, H, W]
__device__ float         g_ca [NF*FR1];   // conv(u_t, W_in) for all t
__device__ unsigned char g_sa [NF*FR1];   // spikes s_a[t] (0/1)
__device__ float         g_cb [NF*FR2];   // conv(s_a[t], W_down, s2)
__device__ float         g_za [FS];       // firing rate a-scale
__device__ float         g_acc[FS];       // sum coef[t]*c_a[t] / norm
__device__ float         g_zb [FS2];      // firing rate b-scale
__device__ float         g_tmp[FS2];      // conv(z_b, W_bb)

// -------- packed f32x2 helpers ---------------------------------------------
__device__ __forceinline__ u64 dup2(float v) {          // {v, v}
    u64 r;
    asm("mov.b64 %0, {%1, %1};" : "=l"(r) : "f"(v));
    return r;
}
__device__ __forceinline__ void unpack2(u64 v, float& lo, float& hi) {
    asm("mov.b64 {%0, %1}, %2;" : "=f"(lo), "=f"(hi) : "l"(v));
}
__device__ __forceinline__ u64 fma2(u64 a, u64 b, u64 c) {
    u64 d;
    asm("fma.rn.f32x2 %0, %1, %2, %3;" : "=l"(d) : "l"(a), "l"(b), "l"(c));
    return d;
}

// -------- transpose u[B,C,H,W,T] -> g_utr[(t*B+b),C,H,W] --------------------
__global__ void __launch_bounds__(256) transpose_u(const float* __restrict__ u) {
    __shared__ float sm[8*32*TT];  // 7680 floats
    const int bid = blockIdx.x;
    const int b  = bid >> 8;
    const int c  = (bid >> 2) & 63;
    const int hg = bid & 3;
    const long long base = ((long long)(b*CC + c)*32 + hg*8) * (32*TT);
    for (int i = threadIdx.x; i < 8*32*TT; i += 256) sm[i] = u[base + i];
    __syncthreads();
    for (int i = threadIdx.x; i < 8*32*TT; i += 256) {
        int t  = i >> 8;
        int hw = i & 255;
        g_utr[((long long)(t*BB + b)*CC + c)*(HH*WW) + hg*256 + hw] = sm[hw*TT + t];
    }
}

// ============================================================================
// stride-1 3x3 conv, SAME padding (pad_lo=1), OIHW weights.
// smem inputs plain f32 (LDS.32 + register dup); weights via LDS.128 (2 pairs).
// 8 warps x 8 c_out each (4 f32x2 pairs). RB=4 output rows per thread.
// ============================================================================
template<int HI, int WI, typename Tin, bool FUSE>
__global__ void __launch_bounds__(256, 2) conv_s1(const Tin* __restrict__ in,
                                                  const float* __restrict__ wts,
                                                  float* __restrict__ out,
                                                  const float* __restrict__ addend) {
    constexpr int HO = HI, WO = WI;
    constexpr int XPT  = (WO >= 32) ? 32 : WO;
    constexpr int LSPL = 32 / XPT;
    constexpr int RB   = 4;
    constexpr int RBL  = RB * LSPL;
    constexpr int IN_ROWS = RBL + 2;
    constexpr int IN_COLS = WI + 2;
    constexpr int CKN = 8;
    constexpr int NR  = RB + 2;

    __shared__ float ism[CKN][IN_ROWS][IN_COLS];
    __shared__ alignas(16) float wsm[CKN][9][64];

    const int f     = blockIdx.x;
    const int r0blk = blockIdx.y * RBL;
    const int lane  = threadIdx.x & 31;
    const int warp  = threadIdx.x >> 5;
    const int x     = lane % XPT;
    const int ysub  = lane / XPT;
    const int co0   = warp * 8;
    const int rbase = r0blk + ysub * RB;

    u64 acc[4][RB];
#pragma unroll
    for (int p = 0; p < 4; ++p)
#pragma unroll
        for (int r = 0; r < RB; ++r) acc[p][r] = 0ULL;

    const long long inbase = (long long)f * CC * HI * WI;

    for (int cc = 0; cc < CC; cc += CKN) {
        for (int i = threadIdx.x; i < CKN*9*64; i += 256) {
            int ci  = i / 576;
            int rem = i - ci*576;
            int tap = rem >> 6;
            int co  = rem & 63;
            wsm[ci][tap][co] = wts[(co*CC + cc + ci)*9 + tap];
        }
        for (int i = threadIdx.x; i < CKN*IN_ROWS*IN_COLS; i += 256) {
            int ci  = i / (IN_ROWS*IN_COLS);
            int rem = i - ci*(IN_ROWS*IN_COLS);
            int r   = rem / IN_COLS;
            int c2  = rem - r*IN_COLS;
            int gy = r0blk - 1 + r, gx = c2 - 1;
            float v = 0.f;
            if ((unsigned)gy < (unsigned)HI && (unsigned)gx < (unsigned)WI)
                v = (float)in[inbase + (long long)(cc+ci)*(HI*WI) + gy*WI + gx];
            ism[ci][r][c2] = v;
        }
        __syncthreads();

#pragma unroll 2
        for (int ci = 0; ci < CKN; ++ci) {
            u64 bv[NR][3];
#pragma unroll
            for (int j = 0; j < NR; ++j) {
                const int srow = ysub*RB + j;
#pragma unroll
                for (int kx = 0; kx < 3; ++kx)
                    bv[j][kx] = dup2(ism[ci][srow][x + kx]);
            }
#pragma unroll
            for (int g = 0; g < 2; ++g) {
#pragma unroll
                for (int ky = 0; ky < 3; ++ky) {
#pragma unroll
                    for (int kx = 0; kx < 3; ++kx) {
                        const ulonglong2 w = *reinterpret_cast<const ulonglong2*>(
                            &wsm[ci][3*ky + kx][co0 + 4*g]);
#pragma unroll
                        for (int r = 0; r < RB; ++r) {
                            acc[2*g][r]   = fma2(bv[r+ky][kx], w.x, acc[2*g][r]);
                            acc[2*g+1][r] = fma2(bv[r+ky][kx], w.y, acc[2*g+1][r]);
                        }
                    }
                }
            }
        }
        __syncthreads();
    }

#pragma unroll
    for (int p = 0; p < 4; ++p) {
#pragma unroll
        for (int r = 0; r < RB; ++r) {
            float lo, hi;
            unpack2(acc[p][r], lo, hi);
            const int oy = rbase + r;
            const long long o0 = (long long)f*CC*HO*WO
                               + (long long)(co0 + 2*p)*HO*WO + oy*WO + x;
            if (FUSE) {
                lo += addend[o0];
                hi += addend[o0 + HO*WO];
                lo = fminf(fmaxf(lo, 0.f), 1.f);
                hi = fminf(fmaxf(hi, 0.f), 1.f);
            }
            out[o0]         = lo;
            out[o0 + HO*WO] = hi;
        }
    }
}

// ============================================================================
// stride-2 3x3 conv 32x32 -> 16x16, SAME (pad_lo=0, pad_hi=1 — JAX asymmetric).
// Deinterleaved even/odd column planes: conflict-free lane reads.
//   out col x taps: in[2x]=evn[x], in[2x+1]=odd[x], in[2x+2]=evn[x+1]
// 8 warps x 8 c_out; warp = 16 x-lanes x 2 ysub; RB=4 rows/thread; grid.y=2.
// ============================================================================
template<typename Tin, bool FUSE>
__global__ void __launch_bounds__(256, 2) conv_s2(const Tin* __restrict__ in,
                                                  const float* __restrict__ wts,
                                                  float* __restrict__ out,
                                                  const float* __restrict__ addend) {
    constexpr int HI = 32, WI = 32, HO = 16, WO = 16;
    constexpr int RB = 4;
    constexpr int IN_ROWS = 17;           // 2*8+1 input rows per block
    constexpr int CKN = 8;
    constexpr int NR = 2*RB + 1;          // 9 input rows per thread

    __shared__ float evn[CKN][IN_ROWS][17];   // row stride 17 floats
    __shared__ float odd[CKN][IN_ROWS][16];   // row stride 16: disjoint half-warp banks
    __shared__ alignas(16) float wsm[CKN][9][64];

    const int f    = blockIdx.x;
    const int yb   = blockIdx.y;          // 0/1
    const int lane = threadIdx.x & 31;
    const int warp = threadIdx.x >> 5;
    const int x    = lane & 15;
    const int ysub = lane >> 4;
    const int co0  = warp * 8;
    const int rbase = yb*8 + ysub*RB;
    const int r0in  = 16*yb;

    u64 acc[4][RB];
#pragma unroll
    for (int p = 0; p < 4; ++p)
#pragma unroll
        for (int r = 0; r < RB; ++r) acc[p][r] = 0ULL;

    const long long inbase = (long long)f * CC * HI * WI;

    for (int cc = 0; cc < CC; cc += CKN) {
        for (int i = threadIdx.x; i < CKN*9*64; i += 256) {
            int ci  = i / 576;
            int rem = i - ci*576;
            int tap = rem >> 6;
            int co  = rem & 63;
            wsm[ci][tap][co] = wts[(co*CC + cc + ci)*9 + tap];
        }
        // input rows r0in..r0in+16, cols 0..32 (col 32 & row 32 are zero pad)
        for (int i = threadIdx.x; i < CKN*IN_ROWS*33; i += 256) {
            int ci  = i / (IN_ROWS*33);
            int rem = i - ci*(IN_ROWS*33);
            int r   = rem / 33;
            int c2  = rem - r*33;
            int gy = r0in + r;
            float v = 0.f;
            if (gy < HI && c2 < WI)
                v = (float)in[inbase + (long long)(cc+ci)*(HI*WI) + gy*WI + c2];
            if (c2 & 1) odd[ci][r][c2 >> 1] = v;
            else        evn[ci][r][c2 >> 1] = v;
        }
        __syncthreads();

#pragma unroll 2
        for (int ci = 0; ci < CKN; ++ci) {
            u64 bv[NR][3];
#pragma unroll
            for (int j = 0; j < NR; ++j) {
                const int srow = 8*ysub + j;
                bv[j][0] = dup2(evn[ci][srow][x]);
                bv[j][1] = dup2(odd[ci][srow][x]);
                bv[j][2] = dup2(evn[ci][srow][x + 1]);
            }
#pragma unroll
            for (int g = 0; g < 2; ++g) {
#pragma unroll
                for (int ky = 0; ky < 3; ++ky) {
#pragma unroll
                    for (int kx = 0; kx < 3; ++kx) {
                        const ulonglong2 w = *reinterpret_cast<const ulonglong2*>(
                            &wsm[ci][3*ky + kx][co0 + 4*g]);
#pragma unroll
                        for (int r = 0; r < RB; ++r) {
                            acc[2*g][r]   = fma2(bv[2*r+ky][kx], w.x, acc[2*g][r]);
                            acc[2*g+1][r] = fma2(bv[2*r+ky][kx], w.y, acc[2*g+1][r]);
                        }
                    }
                }
            }
        }
        __syncthreads();
    }

#pragma unroll
    for (int p = 0; p < 4; ++p) {
#pragma unroll
        for (int r = 0; r < RB; ++r) {
            float lo, hi;
            unpack2(acc[p][r], lo, hi);
            const int oy = rbase + r;
            const long long o0 = (long long)f*CC*HO*WO
                               + (long long)(co0 + 2*p)*HO*WO + oy*WO + x;
            if (FUSE) {
                lo += addend[o0];
                hi += addend[o0 + HO*WO];
                lo = fminf(fmaxf(lo, 0.f), 1.f);
                hi = fminf(fmaxf(hi, 0.f), 1.f);
            }
            out[o0]         = lo;
            out[o0 + HO*WO] = hi;
        }
    }
}

// -------- scan A: LIF over t (elementwise) + fused u_bar weighted conv sum --
__global__ void __launch_bounds__(256) scanA_kernel() {
    const int p = blockIdx.x * blockDim.x + threadIdx.x;
    float coef[TT];
    float pw = 1.f;
#pragma unroll
    for (int k = 1; k <= TT-1; ++k) { pw *= 0.9f; coef[TT-1-k] = pw; }
    coef[TT-1] = 1.0f + pw * 0.9f;
    const float norm = (float)((1.0 - pow(0.9, (double)(TT+1))) / (1.0 - 0.9));

    float v = 0.f, ssum = 0.f, ac = 0.f;
#pragma unroll
    for (int t = 0; t < TT; ++t) {
        const float cv = g_ca[(long long)t*FS + p];
        ac = fmaf(coef[t], cv, ac);
        v = 0.5f*v + cv;
        const float s = (v >= 1.0f) ? 1.0f : 0.0f;
        v -= s;
        ssum += s;
        g_sa[(long long)t*FS + p] = (unsigned char)s;
    }
    g_za[p]  = ssum / 30.0f;
    g_acc[p] = ac / norm;
}

// -------- scan B: LIF over t at half resolution ----------------------------
__global__ void __launch_bounds__(256) scanB_kernel() {
    const int p = blockIdx.x * blockDim.x + threadIdx.x;
    float v = 0.f, ssum = 0.f;
#pragma unroll
    for (int t = 0; t < TT; ++t) {
        const float cv = g_cb[(long long)t*FS2 + p];
        v = 0.5f*v + cv;
        const float s = (v >= 1.0f) ? 1.0f : 0.0f;
        v -= s;
        ssum += s;
    }
    g_zb[p] = ssum / 30.0f;
}

// ---------------------------------------------------------------------------
extern "C" void kernel_launch(void* const* d_in, const int* in_sizes, int n_in,
                              void* d_out, int out_size) {
    const float* u      = (const float*)d_in[0];
    const float* W_in   = (const float*)d_in[1];
    const float* W_aa   = (const float*)d_in[2];
    const float* W_down = (const float*)d_in[3];
    const float* W_bb   = (const float*)d_in[4];
    float* out = (float*)d_out;

    float *p_utr, *p_ca, *p_cb, *p_za, *p_acc, *p_zb, *p_tmp;
    unsigned char *p_sa;
    cudaGetSymbolAddress((void**)&p_utr, g_utr);
    cudaGetSymbolAddress((void**)&p_ca,  g_ca);
    cudaGetSymbolAddress((void**)&p_sa,  g_sa);
    cudaGetSymbolAddress((void**)&p_cb,  g_cb);
    cudaGetSymbolAddress((void**)&p_za,  g_za);
    cudaGetSymbolAddress((void**)&p_acc, g_acc);
    cudaGetSymbolAddress((void**)&p_zb,  g_zb);
    cudaGetSymbolAddress((void**)&p_tmp, g_tmp);

    // 1. transpose u -> frame-major
    transpose_u<<<BB*CC*4, 256>>>(u);
    // 2. c_a[t] = conv(u_t, W_in) for all 480 frames
    conv_s1<32,32,float,false><<<dim3(NF,8), 256>>>(p_utr, W_in, p_ca, nullptr);
    // 3. LIF scan A (spikes + rates + fused u_bar-conv sum)
    scanA_kernel<<<FS/256, 256>>>();
    // 4. c_b[t] = conv(s_a[t], W_down, stride2) for all 480 frames
    conv_s2<unsigned char,false><<<dim3(NF,2), 256>>>(p_sa, W_down, p_cb, nullptr);
    // 5. LIF scan B
    scanB_kernel<<<FS2/256, 256>>>();
    // 6. a = clip(acc + conv(z_a, W_aa))            -> d_out[0 : FS)
    conv_s1<32,32,float,true><<<dim3(BB,8), 256>>>(p_za, W_aa, out, p_acc);
    // 7a. tmp = conv(z_b, W_bb)  (stride-1 on 16x16)
    conv_s1<16,16,float,false><<<dim3(BB,2), 256>>>(p_zb, W_bb, p_tmp, nullptr);
    // 7b. b = clip(conv(a, W_down, stride2) + tmp)  -> d_out[FS : FS+FS2)
    conv_s2<float,true><<<dim3(BB,2), 256>>>(out, W_down, out + FS, p_tmp);
}

// round 6
// speedup vs baseline: 1.2416x; 1.0858x over previous
#include <cuda_runtime.h>
#include <cstdint>
#include <math.h>

// Problem dims (fixed by the dataset)
#define BB 16
#define CC 64
#define HH 32
#define WW 32
#define TT 30
#define NF (TT*BB)          // 480 frames
#define FR1 (CC*HH*WW)      // 65536 elements per 32x32 frame
#define FR2 (CC*16*16)      // 16384 elements per 16x16 frame
#define FS  (BB*FR1)        // 1048576  (one [B,C,H,W] tensor)
#define FS2 (BB*FR2)        // 262144   (one [B,C,H/2,W/2] tensor)

typedef unsigned long long u64;

// -------- scratch (device globals: the sanctioned no-alloc workaround) ------
__device__ float         g_utr[NF*FR1];   // u transposed to [t*B+b, C, H, W]
__device__ float         g_ca [NF*FR1];   // conv(u_t, W_in) for all t
__device__ unsigned char g_sa [NF*FR1];   // spikes s_a[t] (0/1)
__device__ float         g_cb [NF*FR2];   // conv(s_a[t], W_down, s2)
__device__ float         g_za [FS];       // firing rate a-scale
__device__ float         g_acc[FS];       // sum coef[t]*c_a[t] / norm
__device__ float         g_zb [FS2];      // firing rate b-scale
__device__ float         g_tmp[FS2];      // conv(z_b, W_bb)

// -------- packed f32x2 helpers ---------------------------------------------
__device__ __forceinline__ u64 dup2(float v) {          // {v, v}
    u64 r;
    asm("mov.b64 %0, {%1, %1};" : "=l"(r) : "f"(v));
    return r;
}
__device__ __forceinline__ void unpack2(u64 v, float& lo, float& hi) {
    asm("mov.b64 {%0, %1}, %2;" : "=f"(lo), "=f"(hi) : "l"(v));
}
__device__ __forceinline__ u64 fma2(u64 a, u64 b, u64 c) {
    u64 d;
    asm("fma.rn.f32x2 %0, %1, %2, %3;" : "=l"(d) : "l"(a), "l"(b), "l"(c));
    return d;
}

// -------- transpose u[B,C,H,W,T] -> g_utr[(t*B+b),C,H,W] --------------------
__global__ void __launch_bounds__(256) transpose_u(const float* __restrict__ u) {
    __shared__ float sm[8*32*TT];  // 7680 floats
    const int bid = blockIdx.x;
    const int b  = bid >> 8;
    const int c  = (bid >> 2) & 63;
    const int hg = bid & 3;
    const long long base = ((long long)(b*CC + c)*32 + hg*8) * (32*TT);
    for (int i = threadIdx.x; i < 8*32*TT; i += 256) sm[i] = u[base + i];
    __syncthreads();
    for (int i = threadIdx.x; i < 8*32*TT; i += 256) {
        int t  = i >> 8;
        int hw = i & 255;
        g_utr[((long long)(t*BB + b)*CC + c)*(HH*WW) + hg*256 + hw] = sm[hw*TT + t];
    }
}

// ============================================================================
// stride-1 3x3 conv, SAME padding (pad_lo=1), OIHW weights.
// 128-thread blocks, 4 warps; each warp computes 16 c_out (8 f32x2 pairs).
// Each input value loaded once feeds 16 FMAs -> high ILP; weight LDS.128 are
// warp-uniform (broadcast, ~free). 4 CTAs/SM.
// ============================================================================
template<int HI, int WI, typename Tin, bool FUSE>
__global__ void __launch_bounds__(128, 4) conv_s1(const Tin* __restrict__ in,
                                                  const float* __restrict__ wts,
                                                  float* __restrict__ out,
                                                  const float* __restrict__ addend) {
    constexpr int HO = HI, WO = WI;
    constexpr int XPT  = (WO >= 32) ? 32 : WO;     // x lanes per warp
    constexpr int LSPL = 32 / XPT;                 // 1 or 2 row-splits
    constexpr int RB   = 4;
    constexpr int RBL  = RB * LSPL;                // rows per block
    constexpr int IN_ROWS = RBL + 2;
    constexpr int IN_COLS = WI + 2;
    constexpr int CKN = 8;
    constexpr int NR  = RB + 2;

    __shared__ float ism[CKN][IN_ROWS][IN_COLS];
    __shared__ alignas(16) float wsm[CKN][9][64];

    const int f     = blockIdx.x;
    const int r0blk = blockIdx.y * RBL;
    const int lane  = threadIdx.x & 31;
    const int warp  = threadIdx.x >> 5;            // 0..3
    const int x     = lane % XPT;
    const int ysub  = lane / XPT;
    const int co0   = warp * 16;                   // 16 c_out per warp
    const int rbase = r0blk + ysub * RB;

    u64 acc[8][RB];
#pragma unroll
    for (int p = 0; p < 8; ++p)
#pragma unroll
        for (int r = 0; r < RB; ++r) acc[p][r] = 0ULL;

    const long long inbase = (long long)f * CC * HI * WI;

    for (int cc = 0; cc < CC; cc += CKN) {
        for (int i = threadIdx.x; i < CKN*9*64; i += 128) {
            int ci  = i / 576;
            int rem = i - ci*576;
            int tap = rem >> 6;
            int co  = rem & 63;
            wsm[ci][tap][co] = wts[(co*CC + cc + ci)*9 + tap];
        }
        for (int i = threadIdx.x; i < CKN*IN_ROWS*IN_COLS; i += 128) {
            int ci  = i / (IN_ROWS*IN_COLS);
            int rem = i - ci*(IN_ROWS*IN_COLS);
            int r   = rem / IN_COLS;
            int c2  = rem - r*IN_COLS;
            int gy = r0blk - 1 + r, gx = c2 - 1;
            float v = 0.f;
            if ((unsigned)gy < (unsigned)HI && (unsigned)gx < (unsigned)WI)
                v = (float)in[inbase + (long long)(cc+ci)*(HI*WI) + gy*WI + gx];
            ism[ci][r][c2] = v;
        }
        __syncthreads();

#pragma unroll 2
        for (int ci = 0; ci < CKN; ++ci) {
            u64 bv[NR][3];
#pragma unroll
            for (int j = 0; j < NR; ++j) {
                const int srow = ysub*RB + j;
#pragma unroll
                for (int kx = 0; kx < 3; ++kx)
                    bv[j][kx] = dup2(ism[ci][srow][x + kx]);
            }
#pragma unroll
            for (int g = 0; g < 4; ++g) {          // 4 groups of 4 c_out
#pragma unroll
                for (int ky = 0; ky < 3; ++ky) {
#pragma unroll
                    for (int kx = 0; kx < 3; ++kx) {
                        const ulonglong2 w = *reinterpret_cast<const ulonglong2*>(
                            &wsm[ci][3*ky + kx][co0 + 4*g]);
#pragma unroll
                        for (int r = 0; r < RB; ++r) {
                            acc[2*g][r]   = fma2(bv[r+ky][kx], w.x, acc[2*g][r]);
                            acc[2*g+1][r] = fma2(bv[r+ky][kx], w.y, acc[2*g+1][r]);
                        }
                    }
                }
            }
        }
        __syncthreads();
    }

#pragma unroll
    for (int p = 0; p < 8; ++p) {
#pragma unroll
        for (int r = 0; r < RB; ++r) {
            float lo, hi;
            unpack2(acc[p][r], lo, hi);
            const int oy = rbase + r;
            const long long o0 = (long long)f*CC*HO*WO
                               + (long long)(co0 + 2*p)*HO*WO + oy*WO + x;
            if (FUSE) {
                lo += addend[o0];
                hi += addend[o0 + HO*WO];
                lo = fminf(fmaxf(lo, 0.f), 1.f);
                hi = fminf(fmaxf(hi, 0.f), 1.f);
            }
            out[o0]         = lo;
            out[o0 + HO*WO] = hi;
        }
    }
}

// ============================================================================
// stride-2 3x3 conv 32x32 -> 16x16, SAME (pad_lo=0, pad_hi=1 — JAX asymmetric).
// Deinterleaved even/odd column planes: conflict-free lane reads.
//   out col x taps: in[2x]=evn[x], in[2x+1]=odd[x], in[2x+2]=evn[x+1]
// 128-thread blocks, 4 warps x 16 c_out; warp = 16 x-lanes x 2 ysub; RB=2.
// Block covers 4 output rows; grid.y = 4. 4 CTAs/SM.
// ============================================================================
template<typename Tin, bool FUSE>
__global__ void __launch_bounds__(128, 4) conv_s2(const Tin* __restrict__ in,
                                                  const float* __restrict__ wts,
                                                  float* __restrict__ out,
                                                  const float* __restrict__ addend) {
    constexpr int HI = 32, WI = 32, HO = 16, WO = 16;
    constexpr int RB = 2;
    constexpr int RBL = 4;                // 2 ysub * RB output rows per block
    constexpr int IN_ROWS = 2*RBL + 1;    // 9 input rows per block
    constexpr int CKN = 8;
    constexpr int NR = 2*RB + 1;          // 5 input rows per thread

    __shared__ float evn[CKN][IN_ROWS][17];   // row stride 17 floats
    __shared__ float odd[CKN][IN_ROWS][16];   // row stride 16: disjoint half-warp banks
    __shared__ alignas(16) float wsm[CKN][9][64];

    const int f    = blockIdx.x;
    const int yb   = blockIdx.y;          // 0..3
    const int lane = threadIdx.x & 31;
    const int warp = threadIdx.x >> 5;    // 0..3
    const int x    = lane & 15;
    const int ysub = lane >> 4;
    const int co0  = warp * 16;
    const int rbase = yb*RBL + ysub*RB;
    const int r0in  = 8*yb;

    u64 acc[8][RB];
#pragma unroll
    for (int p = 0; p < 8; ++p)
#pragma unroll
        for (int r = 0; r < RB; ++r) acc[p][r] = 0ULL;

    const long long inbase = (long long)f * CC * HI * WI;

    for (int cc = 0; cc < CC; cc += CKN) {
        for (int i = threadIdx.x; i < CKN*9*64; i += 128) {
            int ci  = i / 576;
            int rem = i - ci*576;
            int tap = rem >> 6;
            int co  = rem & 63;
            wsm[ci][tap][co] = wts[(co*CC + cc + ci)*9 + tap];
        }
        // input rows r0in..r0in+8, cols 0..32 (col 32 & row 32 are zero pad)
        for (int i = threadIdx.x; i < CKN*IN_ROWS*33; i += 128) {
            int ci  = i / (IN_ROWS*33);
            int rem = i - ci*(IN_ROWS*33);
            int r   = rem / 33;
            int c2  = rem - r*33;
            int gy = r0in + r;
            float v = 0.f;
            if (gy < HI && c2 < WI)
                v = (float)in[inbase + (long long)(cc+ci)*(HI*WI) + gy*WI + c2];
            if (c2 & 1) odd[ci][r][c2 >> 1] = v;
            else        evn[ci][r][c2 >> 1] = v;
        }
        __syncthreads();

#pragma unroll 2
        for (int ci = 0; ci < CKN; ++ci) {
            u64 bv[NR][3];
#pragma unroll
            for (int j = 0; j < NR; ++j) {
                const int srow = 2*RB*ysub + j;   // ysub*4 + j
                bv[j][0] = dup2(evn[ci][srow][x]);
                bv[j][1] = dup2(odd[ci][srow][x]);
                bv[j][2] = dup2(evn[ci][srow][x + 1]);
            }
#pragma unroll
            for (int g = 0; g < 4; ++g) {
#pragma unroll
                for (int ky = 0; ky < 3; ++ky) {
#pragma unroll
                    for (int kx = 0; kx < 3; ++kx) {
                        const ulonglong2 w = *reinterpret_cast<const ulonglong2*>(
                            &wsm[ci][3*ky + kx][co0 + 4*g]);
#pragma unroll
                        for (int r = 0; r < RB; ++r) {
                            acc[2*g][r]   = fma2(bv[2*r+ky][kx], w.x, acc[2*g][r]);
                            acc[2*g+1][r] = fma2(bv[2*r+ky][kx], w.y, acc[2*g+1][r]);
                        }
                    }
                }
            }
        }
        __syncthreads();
    }

#pragma unroll
    for (int p = 0; p < 8; ++p) {
#pragma unroll
        for (int r = 0; r < RB; ++r) {
            float lo, hi;
            unpack2(acc[p][r], lo, hi);
            const int oy = rbase + r;
            const long long o0 = (long long)f*CC*HO*WO
                               + (long long)(co0 + 2*p)*HO*WO + oy*WO + x;
            if (FUSE) {
                lo += addend[o0];
                hi += addend[o0 + HO*WO];
                lo = fminf(fmaxf(lo, 0.f), 1.f);
                hi = fminf(fmaxf(hi, 0.f), 1.f);
            }
            out[o0]         = lo;
            out[o0 + HO*WO] = hi;
        }
    }
}

// -------- scan A: LIF over t (elementwise) + fused u_bar weighted conv sum --
__global__ void __launch_bounds__(256) scanA_kernel() {
    const int p = blockIdx.x * blockDim.x + threadIdx.x;
    float coef[TT];
    float pw = 1.f;
#pragma unroll
    for (int k = 1; k <= TT-1; ++k) { pw *= 0.9f; coef[TT-1-k] = pw; }
    coef[TT-1] = 1.0f + pw * 0.9f;
    const float norm = (float)((1.0 - pow(0.9, (double)(TT+1))) / (1.0 - 0.9));

    float v = 0.f, ssum = 0.f, ac = 0.f;
#pragma unroll
    for (int t = 0; t < TT; ++t) {
        const float cv = g_ca[(long long)t*FS + p];
        ac = fmaf(coef[t], cv, ac);
        v = 0.5f*v + cv;
        const float s = (v >= 1.0f) ? 1.0f : 0.0f;
        v -= s;
        ssum += s;
        g_sa[(long long)t*FS + p] = (unsigned char)s;
    }
    g_za[p]  = ssum / 30.0f;
    g_acc[p] = ac / norm;
}

// -------- scan B: LIF over t at half resolution ----------------------------
__global__ void __launch_bounds__(256) scanB_kernel() {
    const int p = blockIdx.x * blockDim.x + threadIdx.x;
    float v = 0.f, ssum = 0.f;
#pragma unroll
    for (int t = 0; t < TT; ++t) {
        const float cv = g_cb[(long long)t*FS2 + p];
        v = 0.5f*v + cv;
        const float s = (v >= 1.0f) ? 1.0f : 0.0f;
        v -= s;
        ssum += s;
    }
    g_zb[p] = ssum / 30.0f;
}

// ---------------------------------------------------------------------------
extern "C" void kernel_launch(void* const* d_in, const int* in_sizes, int n_in,
                              void* d_out, int out_size) {
    const float* u      = (const float*)d_in[0];
    const float* W_in   = (const float*)d_in[1];
    const float* W_aa   = (const float*)d_in[2];
    const float* W_down = (const float*)d_in[3];
    const float* W_bb   = (const float*)d_in[4];
    float* out = (float*)d_out;

    float *p_utr, *p_ca, *p_cb, *p_za, *p_acc, *p_zb, *p_tmp;
    unsigned char *p_sa;
    cudaGetSymbolAddress((void**)&p_utr, g_utr);
    cudaGetSymbolAddress((void**)&p_ca,  g_ca);
    cudaGetSymbolAddress((void**)&p_sa,  g_sa);
    cudaGetSymbolAddress((void**)&p_cb,  g_cb);
    cudaGetSymbolAddress((void**)&p_za,  g_za);
    cudaGetSymbolAddress((void**)&p_acc, g_acc);
    cudaGetSymbolAddress((void**)&p_zb,  g_zb);
    cudaGetSymbolAddress((void**)&p_tmp, g_tmp);

    // 1. transpose u -> frame-major
    transpose_u<<<BB*CC*4, 256>>>(u);
    // 2. c_a[t] = conv(u_t, W_in) for all 480 frames
    conv_s1<32,32,float,false><<<dim3(NF,8), 128>>>(p_utr, W_in, p_ca, nullptr);
    // 3. LIF scan A (spikes + rates + fused u_bar-conv sum)
    scanA_kernel<<<FS/256, 256>>>();
    // 4. c_b[t] = conv(s_a[t], W_down, stride2) for all 480 frames
    conv_s2<unsigned char,false><<<dim3(NF,4), 128>>>(p_sa, W_down, p_cb, nullptr);
    // 5. LIF scan B
    scanB_kernel<<<FS2/256, 256>>>();
    // 6. a = clip(acc + conv(z_a, W_aa))            -> d_out[0 : FS)
    conv_s1<32,32,float,true><<<dim3(BB,8), 128>>>(p_za, W_aa, out, p_acc);
    // 7a. tmp = conv(z_b, W_bb)  (stride-1 on 16x16)
    conv_s1<16,16,float,false><<<dim3(BB,2), 128>>>(p_zb, W_bb, p_tmp, nullptr);
    // 7b. b = clip(conv(a, W_down, stride2) + tmp)  -> d_out[FS : FS+FS2)
    conv_s2<float,true><<<dim3(BB,4), 128>>>(out, W_down, out + FS, p_tmp);
}

// round 9
// speedup vs baseline: 1.3097x; 1.0549x over previous
#include <cuda_runtime.h>
#include <cstdint>
#include <math.h>

// Problem dims (fixed by the dataset)
#define BB 16
#define CC 64
#define HH 32
#define WW 32
#define TT 30
#define NF (TT*BB)          // 480 frames
#define FR1 (CC*HH*WW)      // 65536 elements per 32x32 frame
#define FR2 (CC*16*16)      // 16384 elements per 16x16 frame
#define FS  (BB*FR1)        // 1048576  (one [B,C,H,W] tensor)
#define FS2 (BB*FR2)        // 262144   (one [B,C,H/2,W/2] tensor)

typedef unsigned long long u64;

// -------- scratch (device globals: the sanctioned no-alloc workaround) ------
__device__ float         g_utr[NF*FR1];   // u transposed to [t*B+b, C, H, W]
__device__ float         g_ca [NF*FR1];   // conv(u_t, W_in) for all t
__device__ unsigned char g_sa [NF*FR1];   // spikes s_a[t] (0/1)
__device__ float         g_cb [NF*FR2];   // conv(s_a[t], W_down, s2)
__device__ float         g_za [FS];       // firing rate a-scale
__device__ float         g_acc[FS];       // sum coef[t]*c_a[t] / norm
__device__ float         g_zb [FS2];      // firing rate b-scale
__device__ float         g_tmp[FS2];      // conv(z_b, W_bb)

// -------- packed f32x2 helpers ---------------------------------------------
__device__ __forceinline__ u64 dup2(float v) {          // {v, v}
    u64 r;
    asm("mov.b64 %0, {%1, %1};" : "=l"(r) : "f"(v));
    return r;
}
__device__ __forceinline__ void unpack2(u64 v, float& lo, float& hi) {
    asm("mov.b64 {%0, %1}, %2;" : "=f"(lo), "=f"(hi) : "l"(v));
}
__device__ __forceinline__ u64 fma2(u64 a, u64 b, u64 c) {
    u64 d;
    asm("fma.rn.f32x2 %0, %1, %2, %3;" : "=l"(d) : "l"(a), "l"(b), "l"(c));
    return d;
}

// -------- transpose u[B,C,H,W,T] -> g_utr[(t*B+b),C,H,W] --------------------
__global__ void __launch_bounds__(256) transpose_u(const float* __restrict__ u) {
    __shared__ float sm[8*32*TT];  // 7680 floats
    const int bid = blockIdx.x;
    const int b  = bid >> 8;
    const int c  = (bid >> 2) & 63;
    const int hg = bid & 3;
    const long long base = ((long long)(b*CC + c)*32 + hg*8) * (32*TT);
    for (int i = threadIdx.x; i < 8*32*TT; i += 256) sm[i] = u[base + i];
    __syncthreads();
    for (int i = threadIdx.x; i < 8*32*TT; i += 256) {
        int t  = i >> 8;
        int hw = i & 255;
        g_utr[((long long)(t*BB + b)*CC + c)*(HH*WW) + hg*256 + hw] = sm[hw*TT + t];
    }
}

// ============================================================================
// stride-1 3x3 conv, SAME padding (pad_lo=1), OIHW weights.
// 128-thread blocks, 4 warps; each warp computes 16 c_out (8 f32x2 pairs).
// Each input value loaded once feeds 16 FMAs -> high ILP; weight LDS.128 are
// warp-uniform (broadcast, ~free). 4 CTAs/SM.   [R6 version — measured win]
// ============================================================================
template<int HI, int WI, typename Tin, bool FUSE>
__global__ void __launch_bounds__(128, 4) conv_s1(const Tin* __restrict__ in,
                                                  const float* __restrict__ wts,
                                                  float* __restrict__ out,
                                                  const float* __restrict__ addend) {
    constexpr int HO = HI, WO = WI;
    constexpr int XPT  = (WO >= 32) ? 32 : WO;     // x lanes per warp
    constexpr int LSPL = 32 / XPT;                 // 1 or 2 row-splits
    constexpr int RB   = 4;
    constexpr int RBL  = RB * LSPL;                // rows per block
    constexpr int IN_ROWS = RBL + 2;
    constexpr int IN_COLS = WI + 2;
    constexpr int CKN = 8;
    constexpr int NR  = RB + 2;

    __shared__ float ism[CKN][IN_ROWS][IN_COLS];
    __shared__ alignas(16) float wsm[CKN][9][64];

    const int f     = blockIdx.x;
    const int r0blk = blockIdx.y * RBL;
    const int lane  = threadIdx.x & 31;
    const int warp  = threadIdx.x >> 5;            // 0..3
    const int x     = lane % XPT;
    const int ysub  = lane / XPT;
    const int co0   = warp * 16;                   // 16 c_out per warp
    const int rbase = r0blk + ysub * RB;

    u64 acc[8][RB];
#pragma unroll
    for (int p = 0; p < 8; ++p)
#pragma unroll
        for (int r = 0; r < RB; ++r) acc[p][r] = 0ULL;

    const long long inbase = (long long)f * CC * HI * WI;

    for (int cc = 0; cc < CC; cc += CKN) {
        for (int i = threadIdx.x; i < CKN*9*64; i += 128) {
            int ci  = i / 576;
            int rem = i - ci*576;
            int tap = rem >> 6;
            int co  = rem & 63;
            wsm[ci][tap][co] = wts[(co*CC + cc + ci)*9 + tap];
        }
        for (int i = threadIdx.x; i < CKN*IN_ROWS*IN_COLS; i += 128) {
            int ci  = i / (IN_ROWS*IN_COLS);
            int rem = i - ci*(IN_ROWS*IN_COLS);
            int r   = rem / IN_COLS;
            int c2  = rem - r*IN_COLS;
            int gy = r0blk - 1 + r, gx = c2 - 1;
            float v = 0.f;
            if ((unsigned)gy < (unsigned)HI && (unsigned)gx < (unsigned)WI)
                v = (float)in[inbase + (long long)(cc+ci)*(HI*WI) + gy*WI + gx];
            ism[ci][r][c2] = v;
        }
        __syncthreads();

#pragma unroll 2
        for (int ci = 0; ci < CKN; ++ci) {
            u64 bv[NR][3];
#pragma unroll
            for (int j = 0; j < NR; ++j) {
                const int srow = ysub*RB + j;
#pragma unroll
                for (int kx = 0; kx < 3; ++kx)
                    bv[j][kx] = dup2(ism[ci][srow][x + kx]);
            }
#pragma unroll
            for (int g = 0; g < 4; ++g) {          // 4 groups of 4 c_out
#pragma unroll
                for (int ky = 0; ky < 3; ++ky) {
#pragma unroll
                    for (int kx = 0; kx < 3; ++kx) {
                        const ulonglong2 w = *reinterpret_cast<const ulonglong2*>(
                            &wsm[ci][3*ky + kx][co0 + 4*g]);
#pragma unroll
                        for (int r = 0; r < RB; ++r) {
                            acc[2*g][r]   = fma2(bv[r+ky][kx], w.x, acc[2*g][r]);
                            acc[2*g+1][r] = fma2(bv[r+ky][kx], w.y, acc[2*g+1][r]);
                        }
                    }
                }
            }
        }
        __syncthreads();
    }

#pragma unroll
    for (int p = 0; p < 8; ++p) {
#pragma unroll
        for (int r = 0; r < RB; ++r) {
            float lo, hi;
            unpack2(acc[p][r], lo, hi);
            const int oy = rbase + r;
            const long long o0 = (long long)f*CC*HO*WO
                               + (long long)(co0 + 2*p)*HO*WO + oy*WO + x;
            if (FUSE) {
                lo += addend[o0];
                hi += addend[o0 + HO*WO];
                lo = fminf(fmaxf(lo, 0.f), 1.f);
                hi = fminf(fmaxf(hi, 0.f), 1.f);
            }
            out[o0]         = lo;
            out[o0 + HO*WO] = hi;
        }
    }
}

// ============================================================================
// stride-2 3x3 conv 32x32 -> 16x16, SAME (pad_lo=0, pad_hi=1 — JAX asymmetric).
// [Reverted to the R5 configuration — measured 410us]
// Deinterleaved even/odd column planes: conflict-free lane reads.
//   out col x taps: in[2x]=evn[x], in[2x+1]=odd[x], in[2x+2]=evn[x+1]
// 256 threads, 8 warps x 8 c_out; warp = 16 x-lanes x 2 ysub; RB=4; grid.y=2.
// ============================================================================
template<typename Tin, bool FUSE>
__global__ void __launch_bounds__(256, 2) conv_s2(const Tin* __restrict__ in,
                                                  const float* __restrict__ wts,
                                                  float* __restrict__ out,
                                                  const float* __restrict__ addend) {
    constexpr int HI = 32, WI = 32, HO = 16, WO = 16;
    constexpr int RB = 4;
    constexpr int IN_ROWS = 17;           // 2*8+1 input rows per block
    constexpr int CKN = 8;
    constexpr int NR = 2*RB + 1;          // 9 input rows per thread

    __shared__ float evn[CKN][IN_ROWS][17];   // row stride 17 floats
    __shared__ float odd[CKN][IN_ROWS][16];   // row stride 16: disjoint half-warp banks
    __shared__ alignas(16) float wsm[CKN][9][64];

    const int f    = blockIdx.x;
    const int yb   = blockIdx.y;          // 0/1
    const int lane = threadIdx.x & 31;
    const int warp = threadIdx.x >> 5;
    const int x    = lane & 15;
    const int ysub = lane >> 4;
    const int co0  = warp * 8;
    const int rbase = yb*8 + ysub*RB;
    const int r0in  = 16*yb;

    u64 acc[4][RB];
#pragma unroll
    for (int p = 0; p < 4; ++p)
#pragma unroll
        for (int r = 0; r < RB; ++r) acc[p][r] = 0ULL;

    const long long inbase = (long long)f * CC * HI * WI;

    for (int cc = 0; cc < CC; cc += CKN) {
        for (int i = threadIdx.x; i < CKN*9*64; i += 256) {
            int ci  = i / 576;
            int rem = i - ci*576;
            int tap = rem >> 6;
            int co  = rem & 63;
            wsm[ci][tap][co] = wts[(co*CC + cc + ci)*9 + tap];
        }
        // input rows r0in..r0in+16, cols 0..32 (col 32 & row 32 are zero pad)
        for (int i = threadIdx.x; i < CKN*IN_ROWS*33; i += 256) {
            int ci  = i / (IN_ROWS*33);
            int rem = i - ci*(IN_ROWS*33);
            int r   = rem / 33;
            int c2  = rem - r*33;
            int gy = r0in + r;
            float v = 0.f;
            if (gy < HI && c2 < WI)
                v = (float)in[inbase + (long long)(cc+ci)*(HI*WI) + gy*WI + c2];
            if (c2 & 1) odd[ci][r][c2 >> 1] = v;
            else        evn[ci][r][c2 >> 1] = v;
        }
        __syncthreads();

#pragma unroll 2
        for (int ci = 0; ci < CKN; ++ci) {
            u64 bv[NR][3];
#pragma unroll
            for (int j = 0; j < NR; ++j) {
                const int srow = 8*ysub + j;
                bv[j][0] = dup2(evn[ci][srow][x]);
                bv[j][1] = dup2(odd[ci][srow][x]);
                bv[j][2] = dup2(evn[ci][srow][x + 1]);
            }
#pragma unroll
            for (int g = 0; g < 2; ++g) {
#pragma unroll
                for (int ky = 0; ky < 3; ++ky) {
#pragma unroll
                    for (int kx = 0; kx < 3; ++kx) {
                        const ulonglong2 w = *reinterpret_cast<const ulonglong2*>(
                            &wsm[ci][3*ky + kx][co0 + 4*g]);
#pragma unroll
                        for (int r = 0; r < RB; ++r) {
                            acc[2*g][r]   = fma2(bv[2*r+ky][kx], w.x, acc[2*g][r]);
                            acc[2*g+1][r] = fma2(bv[2*r+ky][kx], w.y, acc[2*g+1][r]);
                        }
                    }
                }
            }
        }
        __syncthreads();
    }

#pragma unroll
    for (int p = 0; p < 4; ++p) {
#pragma unroll
        for (int r = 0; r < RB; ++r) {
            float lo, hi;
            unpack2(acc[p][r], lo, hi);
            const int oy = rbase + r;
            const long long o0 = (long long)f*CC*HO*WO
                               + (long long)(co0 + 2*p)*HO*WO + oy*WO + x;
            if (FUSE) {
                lo += addend[o0];
                hi += addend[o0 + HO*WO];
                lo = fminf(fmaxf(lo, 0.f), 1.f);
                hi = fminf(fmaxf(hi, 0.f), 1.f);
            }
            out[o0]         = lo;
            out[o0 + HO*WO] = hi;
        }
    }
}

// -------- scan A: LIF over t (elementwise) + fused u_bar weighted conv sum --
__global__ void __launch_bounds__(256) scanA_kernel() {
    const int p = blockIdx.x * blockDim.x + threadIdx.x;
    float coef[TT];
    float pw = 1.f;
#pragma unroll
    for (int k = 1; k <= TT-1; ++k) { pw *= 0.9f; coef[TT-1-k] = pw; }
    coef[TT-1] = 1.0f + pw * 0.9f;
    const float norm = (float)((1.0 - pow(0.9, (double)(TT+1))) / (1.0 - 0.9));

    float v = 0.f, ssum = 0.f, ac = 0.f;
#pragma unroll
    for (int t = 0; t < TT; ++t) {
        const float cv = g_ca[(long long)t*FS + p];
        ac = fmaf(coef[t], cv, ac);
        v = 0.5f*v + cv;
        const float s = (v >= 1.0f) ? 1.0f : 0.0f;
        v -= s;
        ssum += s;
        g_sa[(long long)t*FS + p] = (unsigned char)s;
    }
    g_za[p]  = ssum / 30.0f;
    g_acc[p] = ac / norm;
}

// -------- scan B: LIF over t at half resolution ----------------------------
__global__ void __launch_bounds__(256) scanB_kernel() {
    const int p = blockIdx.x * blockDim.x + threadIdx.x;
    float v = 0.f, ssum = 0.f;
#pragma unroll
    for (int t = 0; t < TT; ++t) {
        const float cv = g_cb[(long long)t*FS2 + p];
        v = 0.5f*v + cv;
        const float s = (v >= 1.0f) ? 1.0f : 0.0f;
        v -= s;
        ssum += s;
    }
    g_zb[p] = ssum / 30.0f;
}

// ---------------------------------------------------------------------------
extern "C" void kernel_launch(void* const* d_in, const int* in_sizes, int n_in,
                              void* d_out, int out_size) {
    const float* u      = (const float*)d_in[0];
    const float* W_in   = (const float*)d_in[1];
    const float* W_aa   = (const float*)d_in[2];
    const float* W_down = (const float*)d_in[3];
    const float* W_bb   = (const float*)d_in[4];
    float* out = (float*)d_out;

    float *p_utr, *p_ca, *p_cb, *p_za, *p_acc, *p_zb, *p_tmp;
    unsigned char *p_sa;
    cudaGetSymbolAddress((void**)&p_utr, g_utr);
    cudaGetSymbolAddress((void**)&p_ca,  g_ca);
    cudaGetSymbolAddress((void**)&p_sa,  g_sa);
    cudaGetSymbolAddress((void**)&p_cb,  g_cb);
    cudaGetSymbolAddress((void**)&p_za,  g_za);
    cudaGetSymbolAddress((void**)&p_acc, g_acc);
    cudaGetSymbolAddress((void**)&p_zb,  g_zb);
    cudaGetSymbolAddress((void**)&p_tmp, g_tmp);

    // 1. transpose u -> frame-major
    transpose_u<<<BB*CC*4, 256>>>(u);
    // 2. c_a[t] = conv(u_t, W_in) for all 480 frames
    conv_s1<32,32,float,false><<<dim3(NF,8), 128>>>(p_utr, W_in, p_ca, nullptr);
    // 3. LIF scan A (spikes + rates + fused u_bar-conv sum)
    scanA_kernel<<<FS/256, 256>>>();
    // 4. c_b[t] = conv(s_a[t], W_down, stride2) for all 480 frames
    conv_s2<unsigned char,false><<<dim3(NF,2), 256>>>(p_sa, W_down, p_cb, nullptr);
    // 5. LIF scan B
    scanB_kernel<<<FS2/256, 256>>>();
    // 6. a = clip(acc + conv(z_a, W_aa))            -> d_out[0 : FS)
    conv_s1<32,32,float,true><<<dim3(BB,8), 128>>>(p_za, W_aa, out, p_acc);
    // 7a. tmp = conv(z_b, W_bb)  (stride-1 on 16x16)
    conv_s1<16,16,float,false><<<dim3(BB,2), 128>>>(p_zb, W_bb, p_tmp, nullptr);
    // 7b. b = clip(conv(a, W_down, stride2) + tmp)  -> d_out[FS : FS+FS2)
    conv_s2<float,true><<<dim3(BB,2), 256>>>(out, W_down, out + FS, p_tmp);
}

// round 16
// speedup vs baseline: 1.5365x; 1.1732x over previous
#include <cuda_runtime.h>
#include <cuda_bf16.h>
#include <cstdint>
#include <math.h>

// Problem dims (fixed by the dataset)
#define BB 16
#define CC 64
#define HH 32
#define WW 32
#define TT 30
#define NF (TT*BB)          // 480 frames
#define FR1 (CC*HH*WW)      // 65536 elements per 32x32 frame
#define FR2 (CC*16*16)      // 16384
#define FS  (BB*FR1)        // 1048576
#define FS2 (BB*FR2)        // 262144

typedef unsigned long long u64;

// -------- scratch ----------------------------------------------------------
__device__ float         g_utr[NF*FR1];
__device__ float         g_ca [NF*FR1];
__device__ unsigned char g_sa [NF*FR1];
__device__ float         g_cb [NF*FR2];
__device__ float         g_za [FS];
__device__ float         g_acc[FS];
__device__ float         g_zb [FS2];
__device__ float         g_tmp[FS2];

// repair machinery: list of pixels whose LIF decisions are threshold-marginal
#define RCAP 262144
__device__ int g_cnt;
__device__ int g_list[RCAP];

// -------- packed f32x2 helpers (fp32 convs) --------------------------------
__device__ __forceinline__ u64 dup2(float v) {
    u64 r; asm("mov.b64 %0, {%1, %1};" : "=l"(r) : "f"(v)); return r;
}
__device__ __forceinline__ void unpack2(u64 v, float& lo, float& hi) {
    asm("mov.b64 {%0, %1}, %2;" : "=f"(lo), "=f"(hi) : "l"(v));
}
__device__ __forceinline__ u64 fma2(u64 a, u64 b, u64 c) {
    u64 d; asm("fma.rn.f32x2 %0, %1, %2, %3;" : "=l"(d) : "l"(a), "l"(b), "l"(c)); return d;
}

// -------- mma.sync / ldmatrix helpers (baseline PTX, no "a" features) ------
__device__ __forceinline__ uint32_t smem_u32(const void* p) {
    uint32_t a;
    asm("{ .reg .u64 t; cvta.to.shared.u64 t, %1; cvt.u32.u64 %0, t; }" : "=r"(a) : "l"(p));
    return a;
}
__device__ __forceinline__ void ldsm_x4(uint32_t addr, uint32_t& r0, uint32_t& r1,
                                        uint32_t& r2, uint32_t& r3) {
    asm volatile("ldmatrix.sync.aligned.m8n8.x4.shared.b16 {%0,%1,%2,%3}, [%4];"
                 : "=r"(r0), "=r"(r1), "=r"(r2), "=r"(r3) : "r"(addr));
}
__device__ __forceinline__ void mma_bf16(float* d, const uint32_t* a,
                                         uint32_t b0, uint32_t b1) {
    asm volatile("mma.sync.aligned.m16n8k16.row.col.f32.bf16.bf16.f32 "
                 "{%0,%1,%2,%3},{%4,%5,%6,%7},{%8,%9},{%0,%1,%2,%3};"
                 : "+f"(d[0]), "+f"(d[1]), "+f"(d[2]), "+f"(d[3])
                 : "r"(a[0]), "r"(a[1]), "r"(a[2]), "r"(a[3]), "r"(b0), "r"(b1));
}

// ===================== mma conv1 layout =====================================
// Padded pixel space per frame: P = (y+1)*34 + (x+1), y,x in [-1,32].
// Valid outputs: P in [35,1121). 9 M-tiles of 128 per frame.
// A smem rows r=0..197 -> P = p0-35+r, 64 ci bf16 = 128B/row, XOR-16B swizzle.
// B smem: per tap [co(64)][ci(64)] bf16 rows of 128B (hi then lo, +8192).
#define NTILES   (NF*9)               // 4320
#define A_ROWS   198
#define SM_AHI   0
#define SM_ALO   25344                // 198*128
#define SM_B     50688
#define SM_TOTAL (SM_B + 9*16384)     // 198144
#define SWZ(chunk, r7) (((chunk) ^ (r7)) << 4)

__device__ __forceinline__ void stageA_mma(char* smem, const float* __restrict__ in,
                                           int tile) {
    const int f  = tile / 9;
    const int t  = tile - f * 9;
    const int p0 = 35 + t * 128;
    const float* fin = in + (long long)f * FR1;
    for (int i = threadIdx.x; i < 64 * A_ROWS; i += 256) {
        const int ci = i / A_ROWS;
        const int r  = i - ci * A_ROWS;
        const int P  = p0 - 35 + r;
        const int y  = P / 34 - 1;
        const int x  = P - (y + 1) * 34 - 1;
        float v = 0.f;
        if ((unsigned)x < 32u && (unsigned)y < 32u)
            v = fin[ci * 1024 + y * 32 + x];
        const __nv_bfloat16 h = __float2bfloat16(v);
        const __nv_bfloat16 l = __float2bfloat16(v - __bfloat162float(h));
        const uint32_t off = (uint32_t)(r * 128) + SWZ(ci >> 3, r & 7) + (ci & 7) * 2;
        *(__nv_bfloat16*)(smem + SM_AHI + off) = h;
        *(__nv_bfloat16*)(smem + SM_ALO + off) = l;
    }
}

// Persistent tensor-core conv: 480 frames, 3x3 stride-1 SAME, bf16 hi/lo split.
__global__ void __launch_bounds__(256, 1) conv1_mma(const float* __restrict__ in,
                                                    const float* __restrict__ wts,
                                                    float* __restrict__ out) {
    extern __shared__ char smem[];
    const uint32_t sbase = smem_u32(smem);
    const int tid = threadIdx.x, wid = tid >> 5, lane = tid & 31;

    // ---- stage B once: hi/lo weights, all 9 taps -------------------------
    for (int i = tid; i < 9 * 64 * 64; i += 256) {
        const int tap = i >> 12;
        const int co  = (i >> 6) & 63;
        const int ci  = i & 63;
        const float w = wts[(co * CC + ci) * 9 + tap];
        const __nv_bfloat16 h = __float2bfloat16(w);
        const __nv_bfloat16 l = __float2bfloat16(w - __bfloat162float(h));
        const uint32_t off = SM_B + tap * 16384 + (uint32_t)(co * 128)
                           + SWZ(ci >> 3, co & 7) + (ci & 7) * 2;
        *(__nv_bfloat16*)(smem + off)        = h;
        *(__nv_bfloat16*)(smem + off + 8192) = l;
    }

    int tl = blockIdx.x;
    if (tl < NTILES) stageA_mma(smem, in, tl);
    __syncthreads();

    // per-lane constants for ldmatrix addressing
    const int      mrow  = lane & 15;           // A matrix row within m16
    const int      achp  = lane >> 4;           // A k-chunk parity (0/1)
    const int      cosub = lane & 7;            // B row within n8
    const int      bpar  = (lane >> 3) & 1;     // B k-chunk parity
    const uint32_t breg  = (uint32_t)(lane >> 4) * 8192;  // 0=BHI, 1=BLO
    const int      rb    = 35 + wid * 16 + mrow;

    for (; tl < NTILES; tl += 148) {
        float d[8][4];
#pragma unroll
        for (int n = 0; n < 8; ++n)
#pragma unroll
            for (int q = 0; q < 4; ++q) d[n][q] = 0.f;

#pragma unroll 1
        for (int tap = 0; tap < 9; ++tap) {
            const int r = rb + (tap / 3) * 34 + (tap % 3) - 35;
            const uint32_t arow = sbase + (uint32_t)(r * 128);
            const uint32_t r7   = (uint32_t)(r & 7);
            const uint32_t btap = sbase + SM_B + (uint32_t)tap * 16384 + breg
                                + (uint32_t)(cosub * 128);
#pragma unroll
            for (int kk = 0; kk < 4; ++kk) {
                uint32_t ah[4], al[4];
                const uint32_t ao = arow + SWZ((uint32_t)(2 * kk + achp), r7);
                ldsm_x4(ao,            ah[0], ah[1], ah[2], ah[3]);
                ldsm_x4(ao + SM_ALO,   al[0], al[1], al[2], al[3]);
                const uint32_t bo = btap + SWZ((uint32_t)(2 * kk + bpar), (uint32_t)cosub);
#pragma unroll
                for (int n = 0; n < 8; ++n) {
                    uint32_t b0, b1, b2, b3;      // {Bhi k0-7, Bhi k8-15, Blo k0-7, Blo k8-15}
                    ldsm_x4(bo + (uint32_t)n * 1024, b0, b1, b2, b3);
                    mma_bf16(d[n], ah, b0, b1);   // hi*hi
                    mma_bf16(d[n], ah, b2, b3);   // hi*lo
                    mma_bf16(d[n], al, b0, b1);   // lo*hi
                }
            }
        }

        // ---- writeback ----------------------------------------------------
        const int f  = tl / 9;
        const int t  = tl - f * 9;
        const int p0 = 35 + t * 128;
        const int P0 = p0 + wid * 16 + (lane >> 2);
        const int P1 = P0 + 8;
        const int ya = P0 / 34 - 1, xa = P0 - (ya + 1) * 34 - 1;
        const int yb = P1 / 34 - 1, xb = P1 - (yb + 1) * 34 - 1;
        const bool va = (unsigned)xa < 32u && (unsigned)ya < 32u;
        const bool vb = (unsigned)xb < 32u && (unsigned)yb < 32u;
        float* ob = out + (long long)f * FR1;
        const int tig2 = (lane & 3) * 2;
#pragma unroll
        for (int n = 0; n < 8; ++n) {
            const int co = n * 8 + tig2;
            if (va) {
                ob[co * 1024 + ya * 32 + xa]       = d[n][0];
                ob[(co + 1) * 1024 + ya * 32 + xa] = d[n][1];
            }
            if (vb) {
                ob[co * 1024 + yb * 32 + xb]       = d[n][2];
                ob[(co + 1) * 1024 + yb * 32 + xb] = d[n][3];
            }
        }
        __syncthreads();
        if (tl + 148 < NTILES) stageA_mma(smem, in, tl + 148);
        __syncthreads();
    }
}

// -------- transpose u[B,C,H,W,T] -> g_utr[(t*B+b),C,H,W] --------------------
__global__ void __launch_bounds__(256) transpose_u(const float* __restrict__ u) {
    __shared__ float sm[8*32*TT];
    if (blockIdx.x == 0 && threadIdx.x == 0) g_cnt = 0;   // reset repair list
    const int bid = blockIdx.x;
    const int b  = bid >> 8;
    const int c  = (bid >> 2) & 63;
    const int hg = bid & 3;
    const long long bs = ((long long)(b*CC + c)*32 + hg*8) * (32*TT);
    for (int i = threadIdx.x; i < 8*32*TT; i += 256) sm[i] = u[bs + i];
    __syncthreads();
    for (int i = threadIdx.x; i < 8*32*TT; i += 256) {
        int t  = i >> 8;
        int hw = i & 255;
        g_utr[((long long)(t*BB + b)*CC + c)*(HH*WW) + hg*256 + hw] = sm[hw*TT + t];
    }
}

// ============== fp32 stride-1 conv (small launches) =========================
template<int HI, int WI, typename Tin, bool FUSE>
__global__ void __launch_bounds__(128, 4) conv_s1(const Tin* __restrict__ in,
                                                  const float* __restrict__ wts,
                                                  float* __restrict__ out,
                                                  const float* __restrict__ addend) {
    constexpr int HO = HI, WO = WI;
    constexpr int XPT  = (WO >= 32) ? 32 : WO;
    constexpr int LSPL = 32 / XPT;
    constexpr int RB   = 4;
    constexpr int RBL  = RB * LSPL;
    constexpr int IN_ROWS = RBL + 2;
    constexpr int IN_COLS = WI + 2;
    constexpr int CKN = 8;
    constexpr int NR  = RB + 2;

    __shared__ float ism[CKN][IN_ROWS][IN_COLS];
    __shared__ alignas(16) float wsm[CKN][9][64];

    const int f     = blockIdx.x;
    const int r0blk = blockIdx.y * RBL;
    const int lane  = threadIdx.x & 31;
    const int warp  = threadIdx.x >> 5;
    const int x     = lane % XPT;
    const int ysub  = lane / XPT;
    const int co0   = warp * 16;
    const int rbase = r0blk + ysub * RB;

    u64 acc[8][RB];
#pragma unroll
    for (int p = 0; p < 8; ++p)
#pragma unroll
        for (int r = 0; r < RB; ++r) acc[p][r] = 0ULL;

    const long long inbase = (long long)f * CC * HI * WI;

    for (int cc = 0; cc < CC; cc += CKN) {
        for (int i = threadIdx.x; i < CKN*9*64; i += 128) {
            int ci  = i / 576;
            int rem = i - ci*576;
            int tap = rem >> 6;
            int co  = rem & 63;
            wsm[ci][tap][co] = wts[(co*CC + cc + ci)*9 + tap];
        }
        for (int i = threadIdx.x; i < CKN*IN_ROWS*IN_COLS; i += 128) {
            int ci  = i / (IN_ROWS*IN_COLS);
            int rem = i - ci*(IN_ROWS*IN_COLS);
            int r   = rem / IN_COLS;
            int c2  = rem - r*IN_COLS;
            int gy = r0blk - 1 + r, gx = c2 - 1;
            float v = 0.f;
            if ((unsigned)gy < (unsigned)HI && (unsigned)gx < (unsigned)WI)
                v = (float)in[inbase + (long long)(cc+ci)*(HI*WI) + gy*WI + gx];
            ism[ci][r][c2] = v;
        }
        __syncthreads();

#pragma unroll 2
        for (int ci = 0; ci < CKN; ++ci) {
            u64 bv[NR][3];
#pragma unroll
            for (int j = 0; j < NR; ++j) {
                const int srow = ysub*RB + j;
#pragma unroll
                for (int kx = 0; kx < 3; ++kx)
                    bv[j][kx] = dup2(ism[ci][srow][x + kx]);
            }
#pragma unroll
            for (int g = 0; g < 4; ++g) {
#pragma unroll
                for (int ky = 0; ky < 3; ++ky) {
#pragma unroll
                    for (int kx = 0; kx < 3; ++kx) {
                        const ulonglong2 w = *reinterpret_cast<const ulonglong2*>(
                            &wsm[ci][3*ky + kx][co0 + 4*g]);
#pragma unroll
                        for (int r = 0; r < RB; ++r) {
                            acc[2*g][r]   = fma2(bv[r+ky][kx], w.x, acc[2*g][r]);
                            acc[2*g+1][r] = fma2(bv[r+ky][kx], w.y, acc[2*g+1][r]);
                        }
                    }
                }
            }
        }
        __syncthreads();
    }

#pragma unroll
    for (int p = 0; p < 8; ++p) {
#pragma unroll
        for (int r = 0; r < RB; ++r) {
            float lo, hi;
            unpack2(acc[p][r], lo, hi);
            const int oy = rbase + r;
            const long long o0 = (long long)f*CC*HO*WO
                               + (long long)(co0 + 2*p)*HO*WO + oy*WO + x;
            if (FUSE) {
                lo += addend[o0];
                hi += addend[o0 + HO*WO];
                lo = fminf(fmaxf(lo, 0.f), 1.f);
                hi = fminf(fmaxf(hi, 0.f), 1.f);
            }
            out[o0]         = lo;
            out[o0 + HO*WO] = hi;
        }
    }
}

// ============== fp32 stride-2 conv (spikes + final) — R5 config =============
template<typename Tin, bool FUSE>
__global__ void __launch_bounds__(256, 2) conv_s2(const Tin* __restrict__ in,
                                                  const float* __restrict__ wts,
                                                  float* __restrict__ out,
                                                  const float* __restrict__ addend) {
    constexpr int HI = 32, WI = 32, HO = 16, WO = 16;
    constexpr int RB = 4;
    constexpr int IN_ROWS = 17;
    constexpr int CKN = 8;
    constexpr int NR = 2*RB + 1;

    __shared__ float evn[CKN][IN_ROWS][17];
    __shared__ float odd[CKN][IN_ROWS][16];
    __shared__ alignas(16) float wsm[CKN][9][64];

    const int f    = blockIdx.x;
    const int yb   = blockIdx.y;
    const int lane = threadIdx.x & 31;
    const int warp = threadIdx.x >> 5;
    const int x    = lane & 15;
    const int ysub = lane >> 4;
    const int co0  = warp * 8;
    const int rbase = yb*8 + ysub*RB;
    const int r0in  = 16*yb;

    u64 acc[4][RB];
#pragma unroll
    for (int p = 0; p < 4; ++p)
#pragma unroll
        for (int r = 0; r < RB; ++r) acc[p][r] = 0ULL;

    const long long inbase = (long long)f * CC * HI * WI;

    for (int cc = 0; cc < CC; cc += CKN) {
        for (int i = threadIdx.x; i < CKN*9*64; i += 256) {
            int ci  = i / 576;
            int rem = i - ci*576;
            int tap = rem >> 6;
            int co  = rem & 63;
            wsm[ci][tap][co] = wts[(co*CC + cc + ci)*9 + tap];
        }
        for (int i = threadIdx.x; i < CKN*IN_ROWS*33; i += 256) {
            int ci  = i / (IN_ROWS*33);
            int rem = i - ci*(IN_ROWS*33);
            int r   = rem / 33;
            int c2  = rem - r*33;
            int gy = r0in + r;
            float v = 0.f;
            if (gy < HI && c2 < WI)
                v = (float)in[inbase + (long long)(cc+ci)*(HI*WI) + gy*WI + c2];
            if (c2 & 1) odd[ci][r][c2 >> 1] = v;
            else        evn[ci][r][c2 >> 1] = v;
        }
        __syncthreads();

#pragma unroll 2
        for (int ci = 0; ci < CKN; ++ci) {
            u64 bv[NR][3];
#pragma unroll
            for (int j = 0; j < NR; ++j) {
                const int srow = 8*ysub + j;
                bv[j][0] = dup2(evn[ci][srow][x]);
                bv[j][1] = dup2(odd[ci][srow][x]);
                bv[j][2] = dup2(evn[ci][srow][x + 1]);
            }
#pragma unroll
            for (int g = 0; g < 2; ++g) {
#pragma unroll
                for (int ky = 0; ky < 3; ++ky) {
#pragma unroll
                    for (int kx = 0; kx < 3; ++kx) {
                        const ulonglong2 w = *reinterpret_cast<const ulonglong2*>(
                            &wsm[ci][3*ky + kx][co0 + 4*g]);
#pragma unroll
                        for (int r = 0; r < RB; ++r) {
                            acc[2*g][r]   = fma2(bv[2*r+ky][kx], w.x, acc[2*g][r]);
                            acc[2*g+1][r] = fma2(bv[2*r+ky][kx], w.y, acc[2*g+1][r]);
                        }
                    }
                }
            }
        }
        __syncthreads();
    }

#pragma unroll
    for (int p = 0; p < 4; ++p) {
#pragma unroll
        for (int r = 0; r < RB; ++r) {
            float lo, hi;
            unpack2(acc[p][r], lo, hi);
            const int oy = rbase + r;
            const long long o0 = (long long)f*CC*HO*WO
                               + (long long)(co0 + 2*p)*HO*WO + oy*WO + x;
            if (FUSE) {
                lo += addend[o0];
                hi += addend[o0 + HO*WO];
                lo = fminf(fmaxf(lo, 0.f), 1.f);
                hi = fminf(fmaxf(hi, 0.f), 1.f);
            }
            out[o0]         = lo;
            out[o0 + HO*WO] = hi;
        }
    }
}

// -------- scan A: LIF + u_bar acc + flag threshold-marginal pixels ----------
__global__ void __launch_bounds__(256) scanA_kernel() {
    const int p = blockIdx.x * blockDim.x + threadIdx.x;
    float coef[TT];
    float pw = 1.f;
#pragma unroll
    for (int k = 1; k <= TT-1; ++k) { pw *= 0.9f; coef[TT-1-k] = pw; }
    coef[TT-1] = 1.0f + pw * 0.9f;
    const float norm = (float)((1.0 - pow(0.9, (double)(TT+1))) / (1.0 - 0.9));

    float v = 0.f, ssum = 0.f, ac = 0.f;
    bool flg = false;
#pragma unroll
    for (int t = 0; t < TT; ++t) {
        const float cv = g_ca[(long long)t*FS + p];
        ac = fmaf(coef[t], cv, ac);
        v = 0.5f*v + cv;
        flg = flg || (fabsf(v - 1.0f) < 1e-4f);   // bf16-split error bound << 1e-4
        const float s = (v >= 1.0f) ? 1.0f : 0.0f;
        v -= s;
        ssum += s;
        g_sa[(long long)t*FS + p] = (unsigned char)s;
    }
    g_za[p]  = ssum / 30.0f;
    g_acc[p] = ac / norm;
    if (flg) {
        int i = atomicAdd(&g_cnt, 1);
        if (i < RCAP) g_list[i] = p;
    }
}

// -------- repair: exact fp32 recompute of LIF for flagged pixels ------------
// One warp per flagged pixel; lanes split the 64 input channels.
__global__ void __launch_bounds__(256) repairA(const float* __restrict__ utr,
                                               const float* __restrict__ W_in) {
    const int lane  = threadIdx.x & 31;
    const int wglob = (blockIdx.x * blockDim.x + threadIdx.x) >> 5;
    const int nwarp = (gridDim.x * blockDim.x) >> 5;
    int n = g_cnt; if (n > RCAP) n = RCAP;

    float coef[TT];
    float pw = 1.f;
#pragma unroll
    for (int k = 1; k <= TT-1; ++k) { pw *= 0.9f; coef[TT-1-k] = pw; }
    coef[TT-1] = 1.0f + pw * 0.9f;
    const float norm = (float)((1.0 - pow(0.9, (double)(TT+1))) / (1.0 - 0.9));

    for (int i = wglob; i < n; i += nwarp) {
        const int p  = g_list[i];
        const int b  = p >> 16;
        const int co = (p >> 10) & 63;
        const int y  = (p >> 5) & 31;
        const int x  = p & 31;

        float wv0[9], wv1[9];
#pragma unroll
        for (int tap = 0; tap < 9; ++tap) {
            wv0[tap] = W_in[(co*CC + lane)*9 + tap];
            wv1[tap] = W_in[(co*CC + lane + 32)*9 + tap];
        }

        float v = 0.f, ssum = 0.f, ac = 0.f;
        for (int t = 0; t < TT; ++t) {
            const float* fb = utr + (long long)(t*BB + b) * FR1;
            float part = 0.f;
#pragma unroll
            for (int dy = 0; dy < 3; ++dy) {
                const int yy = y + dy - 1;
                if ((unsigned)yy < 32u) {
                    const float* r0 = fb + lane*1024 + yy*32;
                    const float* r1 = fb + (lane + 32)*1024 + yy*32;
#pragma unroll
                    for (int dx = 0; dx < 3; ++dx) {
                        const int xx = x + dx - 1;
                        if ((unsigned)xx < 32u) {
                            part = fmaf(r0[xx], wv0[dy*3 + dx], part);
                            part = fmaf(r1[xx], wv1[dy*3 + dx], part);
                        }
                    }
                }
            }
#pragma unroll
            for (int o = 16; o; o >>= 1)
                part += __shfl_xor_sync(0xFFFFFFFFu, part, o);
            ac = fmaf(coef[t], part, ac);
            v = 0.5f*v + part;
            const float s = (v >= 1.0f) ? 1.0f : 0.0f;
            v -= s;
            ssum += s;
            if (lane == 0) g_sa[(long long)t*FS + p] = (unsigned char)s;
        }
        if (lane == 0) {
            g_za[p]  = ssum / 30.0f;
            g_acc[p] = ac / norm;
        }
    }
}

// -------- scan B ------------------------------------------------------------
__global__ void __launch_bounds__(256) scanB_kernel() {
    const int p = blockIdx.x * blockDim.x + threadIdx.x;
    float v = 0.f, ssum = 0.f;
#pragma unroll
    for (int t = 0; t < TT; ++t) {
        const float cv = g_cb[(long long)t*FS2 + p];
        v = 0.5f*v + cv;
        const float s = (v >= 1.0f) ? 1.0f : 0.0f;
        v -= s;
        ssum += s;
    }
    g_zb[p] = ssum / 30.0f;
}

// ---------------------------------------------------------------------------
extern "C" void kernel_launch(void* const* d_in, const int* in_sizes, int n_in,
                              void* d_out, int out_size) {
    const float* u      = (const float*)d_in[0];
    const float* W_in   = (const float*)d_in[1];
    const float* W_aa   = (const float*)d_in[2];
    const float* W_down = (const float*)d_in[3];
    const float* W_bb   = (const float*)d_in[4];
    float* out = (float*)d_out;

    float *p_utr, *p_ca, *p_cb, *p_za, *p_acc, *p_zb, *p_tmp;
    unsigned char *p_sa;
    cudaGetSymbolAddress((void**)&p_utr, g_utr);
    cudaGetSymbolAddress((void**)&p_ca,  g_ca);
    cudaGetSymbolAddress((void**)&p_sa,  g_sa);
    cudaGetSymbolAddress((void**)&p_cb,  g_cb);
    cudaGetSymbolAddress((void**)&p_za,  g_za);
    cudaGetSymbolAddress((void**)&p_acc, g_acc);
    cudaGetSymbolAddress((void**)&p_zb,  g_zb);
    cudaGetSymbolAddress((void**)&p_tmp, g_tmp);

    cudaFuncSetAttribute(conv1_mma, cudaFuncAttributeMaxDynamicSharedMemorySize, SM_TOTAL);

    // 1. transpose u -> frame-major (also resets repair-list counter)
    transpose_u<<<BB*CC*4, 256>>>(u);
    // 2. c_a[t] = conv(u_t, W_in) for all 480 frames  (mma.sync bf16-split)
    conv1_mma<<<148, 256, SM_TOTAL>>>(p_utr, W_in, p_ca);
    // 3. LIF scan A (flags threshold-marginal pixels)
    scanA_kernel<<<FS/256, 256>>>();
    // 3b. exact fp32 repair of flagged pixels (spikes, z_a, acc)
    repairA<<<256, 256>>>(p_utr, W_in);
    // 4. c_b[t] = conv(s_a[t], W_down, stride2)
    conv_s2<unsigned char,false><<<dim3(NF,2), 256>>>(p_sa, W_down, p_cb, nullptr);
    // 5. LIF scan B
    scanB_kernel<<<FS2/256, 256>>>();
    // 6. a = clip(acc + conv(z_a, W_aa))            -> d_out[0 : FS)
    conv_s1<32,32,float,true><<<dim3(BB,8), 128>>>(p_za, W_aa, out, p_acc);
    // 7a. tmp = conv(z_b, W_bb)
    conv_s1<16,16,float,false><<<dim3(BB,2), 128>>>(p_zb, W_bb, p_tmp, nullptr);
    // 7b. b = clip(conv(a, W_down, stride2) + tmp)  -> d_out[FS : FS+FS2)
    conv_s2<float,true><<<dim3(BB,2), 256>>>(out, W_down, out + FS, p_tmp);
}